// round 7
// baseline (speedup 1.0000x reference)
#include <cuda_runtime.h>
#include <cuda_bf16.h>
#include <cstdint>

#define BATCH 512
#define T 128
#define C 384
#define H 6
#define D 64
#define HD 384
#define NQKV 1152

typedef unsigned long long ull;

// ---------------- scratch (device globals; no runtime allocation) ----------------
__device__ __align__(256) __nv_bfloat16 g_xhi[(size_t)BATCH * T * C];
__device__ __align__(256) __nv_bfloat16 g_xlo[(size_t)BATCH * T * C];
__device__ __align__(256) __nv_bfloat16 g_wthi[(size_t)NQKV * C];   // [n][k]
__device__ __align__(256) __nv_bfloat16 g_wtlo[(size_t)NQKV * C];
__device__ __align__(256) __nv_bfloat16 g_wpthi[(size_t)HD * C];    // [n][k] = Wp[k][n]
__device__ __align__(256) __nv_bfloat16 g_wptlo[(size_t)HD * C];
// q,k,v all [b][h][t][d] hi/lo  (q pre-scaled by D^-1/2)
__device__ __align__(256) __nv_bfloat16 g_qhi[(size_t)BATCH * H * T * D];
__device__ __align__(256) __nv_bfloat16 g_qlo[(size_t)BATCH * H * T * D];
__device__ __align__(256) __nv_bfloat16 g_khi[(size_t)BATCH * H * T * D];
__device__ __align__(256) __nv_bfloat16 g_klo[(size_t)BATCH * H * T * D];
__device__ __align__(256) __nv_bfloat16 g_vhi[(size_t)BATCH * H * T * D];
__device__ __align__(256) __nv_bfloat16 g_vlo[(size_t)BATCH * H * T * D];
__device__ __align__(256) __nv_bfloat16 g_atthi[(size_t)BATCH * T * HD];
__device__ __align__(256) __nv_bfloat16 g_attlo[(size_t)BATCH * T * HD];

// ---------------- helpers (baseline PTX, compute_103-safe) ----------------
__device__ __forceinline__ uint32_t smem_u32(const void* p) {
    uint32_t a;
    asm("{ .reg .u64 t; cvta.to.shared.u64 t, %1; cvt.u32.u64 %0, t; }" : "=r"(a) : "l"(p));
    return a;
}
__device__ __forceinline__ void ldsm4(uint32_t* r, uint32_t addr) {
    asm volatile("ldmatrix.sync.aligned.m8n8.x4.shared.b16 {%0,%1,%2,%3}, [%4];"
        : "=r"(r[0]), "=r"(r[1]), "=r"(r[2]), "=r"(r[3]) : "r"(addr));
}
__device__ __forceinline__ void ldsm4t(uint32_t* r, uint32_t addr) {
    asm volatile("ldmatrix.sync.aligned.m8n8.x4.trans.shared.b16 {%0,%1,%2,%3}, [%4];"
        : "=r"(r[0]), "=r"(r[1]), "=r"(r[2]), "=r"(r[3]) : "r"(addr));
}
__device__ __forceinline__ void mma16816(float* c, const uint32_t* a, const uint32_t* b) {
    asm volatile("mma.sync.aligned.m16n8k16.row.col.f32.bf16.bf16.f32 "
        "{%0,%1,%2,%3}, {%4,%5,%6,%7}, {%8,%9}, {%0,%1,%2,%3};"
        : "+f"(c[0]), "+f"(c[1]), "+f"(c[2]), "+f"(c[3])
        : "r"(a[0]), "r"(a[1]), "r"(a[2]), "r"(a[3]), "r"(b[0]), "r"(b[1]));
}
__device__ __forceinline__ void cpa16(uint32_t dst, const void* src) {
    asm volatile("cp.async.cg.shared.global [%0], [%1], 16;" :: "r"(dst), "l"(src));
}
#define CPA_COMMIT() asm volatile("cp.async.commit_group;" ::: "memory")
#define CPA_WAIT1()  asm volatile("cp.async.wait_group 1;" ::: "memory")
#define CPA_WAIT0()  asm volatile("cp.async.wait_group 0;" ::: "memory")

__device__ __forceinline__ uint32_t cvt_bf16x2(float lo, float hi) {
    uint32_t r;
    asm("cvt.rn.bf16x2.f32 %0, %1, %2;" : "=r"(r) : "f"(hi), "f"(lo));
    return r;
}
__device__ __forceinline__ float lo_f(uint32_t u) { return __uint_as_float(u << 16); }
__device__ __forceinline__ float hi_f(uint32_t u) { return __uint_as_float(u & 0xFFFF0000u); }
__device__ __forceinline__ void hilo_pair(float a, float b, uint32_t& h, uint32_t& l) {
    h = cvt_bf16x2(a, b);
    l = cvt_bf16x2(a - lo_f(h), b - hi_f(h));
}

// =================================================================================
// Conversion kernels (fp32 -> bf16 hi/lo split)
// =================================================================================
__global__ void conv_x_kernel(const float* __restrict__ x) {
    size_t i = ((size_t)blockIdx.x * 256 + threadIdx.x) * 4;
    float4 v = *(const float4*)(x + i);
    uint32_t h0, l0, h1, l1;
    hilo_pair(v.x, v.y, h0, l0);
    hilo_pair(v.z, v.w, h1, l1);
    *(uint32_t*)(g_xhi + i)     = h0;
    *(uint32_t*)(g_xhi + i + 2) = h1;
    *(uint32_t*)(g_xlo + i)     = l0;
    *(uint32_t*)(g_xlo + i + 2) = l1;
}

__global__ void conv_w_kernel(const float* __restrict__ Wq, const float* __restrict__ Wk,
                              const float* __restrict__ Wv) {
    int idx = blockIdx.x * 256 + threadIdx.x;   // n*C + k
    if (idx >= NQKV * C) return;
    int n = idx / C, k = idx - n * C;
    int which = n / HD, rem = n - which * HD;
    int h = rem >> 6, d = rem & 63;
    const float* W = (which == 0) ? Wq : (which == 1) ? Wk : Wv;
    float v = W[((size_t)h * C + k) * D + d];
    __nv_bfloat16 hi = __float2bfloat16(v);
    g_wthi[idx] = hi;
    g_wtlo[idx] = __float2bfloat16(v - __bfloat162float(hi));
}

__global__ void conv_wp_kernel(const float* __restrict__ Wp) {
    int idx = blockIdx.x * 256 + threadIdx.x;   // n*C + k
    if (idx >= HD * C) return;
    int n = idx / C, k = idx - n * C;
    float v = Wp[(size_t)k * C + n];
    __nv_bfloat16 hi = __float2bfloat16(v);
    g_wpthi[idx] = hi;
    g_wptlo[idx] = __float2bfloat16(v - __bfloat162float(hi));
}

// =================================================================================
// Tensor-core GEMM: Y[128 x 64] = A[128 x 384] @ B[n][k]^T, bf16 3-split.
// LDSM interleaved with MMAs inside each k-step so the tensor pipe starts early.
// =================================================================================
#define STAGE_BYTES 49152
#define GEMM_SMEM (2 * STAGE_BYTES)

template <bool PROJ>
__global__ __launch_bounds__(256, 2)
void mma_gemm(const float* __restrict__ bp, float* __restrict__ out)
{
    extern __shared__ __align__(1024) char sm[];
    const uint32_t smb = smem_u32(sm);
    const int tid = threadIdx.x, wid = tid >> 5, lane = tid & 31;
    const int b = blockIdx.y, n0 = blockIdx.x * 64;
    const int wm = (wid >> 1) * 32;     // 0,32,64,96
    const int wn = (wid & 1) * 32;      // 0,32

    const __nv_bfloat16* __restrict__ Ahi = (PROJ ? g_atthi : g_xhi) + (size_t)b * T * C;
    const __nv_bfloat16* __restrict__ Alo = (PROJ ? g_attlo : g_xlo) + (size_t)b * T * C;
    const __nv_bfloat16* __restrict__ Bhi = (PROJ ? g_wpthi : g_wthi) + (size_t)n0 * C;
    const __nv_bfloat16* __restrict__ Blo = (PROJ ? g_wptlo : g_wtlo) + (size_t)n0 * C;

    const int l_row = tid >> 3;          // 0..31
    const int l_seg = tid & 7;

    auto load_chunk = [&](int c, int s) {
        const int c0 = c * 64;
        const uint32_t sb = smb + s * STAGE_BYTES;
#pragma unroll
        for (int p = 0; p < 4; p++) {
            const int row = l_row + p * 32;
            const uint32_t doff = (uint32_t)(row * 128 + ((l_seg ^ (row & 7)) << 4));
            const size_t soff = (size_t)row * C + c0 + l_seg * 8;
            cpa16(sb + doff,         Ahi + soff);
            cpa16(sb + 16384 + doff, Alo + soff);
        }
#pragma unroll
        for (int p = 0; p < 2; p++) {
            const int row = l_row + p * 32;   // 0..63
            const uint32_t doff = (uint32_t)(row * 128 + ((l_seg ^ (row & 7)) << 4));
            const size_t soff = (size_t)row * C + c0 + l_seg * 8;
            cpa16(sb + 32768 + doff, Bhi + soff);
            cpa16(sb + 40960 + doff, Blo + soff);
        }
        CPA_COMMIT();
    };

    float acc[2][4][4];
#pragma unroll
    for (int i = 0; i < 2; i++)
#pragma unroll
        for (int j = 0; j < 4; j++)
#pragma unroll
            for (int e = 0; e < 4; e++) acc[i][j][e] = 0.f;

    const int rA  = (lane & 7) + ((lane >> 3) & 1) * 8;
    const int khA = lane >> 4;
    const int swA = rA & 7;
    const int rB  = (lane & 7) + (lane >> 4) * 8;
    const int khB = (lane >> 3) & 1;
    const int swB = rB & 7;

    load_chunk(0, 0);
    load_chunk(1, 1);

    for (int c = 0; c < 6; c++) {
        if (c == 5) CPA_WAIT0(); else CPA_WAIT1();
        __syncthreads();

        const uint32_t sb = smb + (c & 1) * STAGE_BYTES;
        const uint32_t aBase = sb + (uint32_t)((wm + rA) * 128);
        const uint32_t bBase = sb + 32768 + (uint32_t)((wn + rB) * 128);

#pragma unroll
        for (int ks = 0; ks < 4; ks++) {
            const uint32_t aoff = (uint32_t)(((ks * 2 + khA) ^ swA) << 4);
            const uint32_t boff = (uint32_t)(((ks * 2 + khB) ^ swB) << 4);
            uint32_t ahi[2][4], alo[2][4], bh[2][4], bl[2][4];
            // operands for pass 1 only
            ldsm4(ahi[0], aBase + aoff);
            ldsm4(bh[0], bBase + boff);
            ldsm4(ahi[1], aBase + 2048 + aoff);
            ldsm4(bh[1], bBase + 2048 + boff);
            // pass 1 starts immediately; bl/alo LDSMs hide under the MMAs
            mma16816(acc[0][0], ahi[0], &bh[0][0]);
            mma16816(acc[0][1], ahi[0], &bh[0][2]);
            ldsm4(bl[0], bBase + 8192 + boff);
            mma16816(acc[0][2], ahi[0], &bh[1][0]);
            mma16816(acc[0][3], ahi[0], &bh[1][2]);
            ldsm4(bl[1], bBase + 8192 + 2048 + boff);
            mma16816(acc[1][0], ahi[1], &bh[0][0]);
            mma16816(acc[1][1], ahi[1], &bh[0][2]);
            ldsm4(alo[0], aBase + 16384 + aoff);
            mma16816(acc[1][2], ahi[1], &bh[1][0]);
            mma16816(acc[1][3], ahi[1], &bh[1][2]);
            ldsm4(alo[1], aBase + 16384 + 2048 + aoff);
            // pass 2: hi * lo
#pragma unroll
            for (int mf = 0; mf < 2; mf++)
#pragma unroll
                for (int nf = 0; nf < 4; nf++)
                    mma16816(acc[mf][nf], ahi[mf], &bl[nf >> 1][(nf & 1) * 2]);
            // pass 3: lo * hi
#pragma unroll
            for (int mf = 0; mf < 2; mf++)
#pragma unroll
                for (int nf = 0; nf < 4; nf++)
                    mma16816(acc[mf][nf], alo[mf], &bh[nf >> 1][(nf & 1) * 2]);
        }
        __syncthreads();
        if (c + 2 < 6) load_chunk(c + 2, (c & 1));
    }

    // ---------------- epilogue ----------------
    const int qrow = lane >> 2;
    const int qcol = (lane & 3) * 2;

    if (PROJ) {
#pragma unroll
        for (int mf = 0; mf < 2; mf++) {
#pragma unroll
            for (int nf = 0; nf < 4; nf++) {
                const int row = wm + mf * 16 + qrow;
                const int col = n0 + wn + nf * 8 + qcol;
                const float2 bb = *(const float2*)(bp + col);
                float* p0 = out + ((size_t)b * T + row) * HD + col;
                float* p1 = out + ((size_t)b * T + row + 8) * HD + col;
                *(float2*)p0 = make_float2(acc[mf][nf][0] + bb.x, acc[mf][nf][1] + bb.y);
                *(float2*)p1 = make_float2(acc[mf][nf][2] + bb.x, acc[mf][nf][3] + bb.y);
            }
        }
    } else {
        const int which = blockIdx.x / 6;       // 0=q,1=k,2=v
        const int hh = blockIdx.x % 6;
        __nv_bfloat16* bh_ = (which == 0) ? g_qhi : (which == 1) ? g_khi : g_vhi;
        __nv_bfloat16* bl_ = (which == 0) ? g_qlo : (which == 1) ? g_klo : g_vlo;
        const float scale = (which == 0) ? 0.125f : 1.0f;   // q pre-scaled by D^-1/2
        const size_t hb = ((size_t)(b * H + hh) * T) * D;
#pragma unroll
        for (int mf = 0; mf < 2; mf++) {
#pragma unroll
            for (int nf = 0; nf < 4; nf++) {
                const int row = wm + mf * 16 + qrow;
                const int dd = wn + nf * 8 + qcol;
                const size_t o0 = hb + (size_t)row * D + dd;
                uint32_t hi, lo;
                hilo_pair(acc[mf][nf][0] * scale, acc[mf][nf][1] * scale, hi, lo);
                *(uint32_t*)(bh_ + o0) = hi;
                *(uint32_t*)(bl_ + o0) = lo;
                hilo_pair(acc[mf][nf][2] * scale, acc[mf][nf][3] * scale, hi, lo);
                *(uint32_t*)(bh_ + o0 + 8 * D) = hi;
                *(uint32_t*)(bl_ + o0 + 8 * D) = lo;
            }
        }
    }
}

// =================================================================================
// MMA attention per (b, h). q pre-scaled; softmax normalization deferred to the
// O epilogue (PV is linear in P). LDSM/MMA interleaved in PV.
// =================================================================================
#define ATTN_SMEM 98304

__global__ __launch_bounds__(256, 1)
void attn_mma()
{
    extern __shared__ __align__(1024) char sm[];
    const uint32_t smb = smem_u32(sm);
    const int tid = threadIdx.x, w = tid >> 5, lane = tid & 31;
    const int b = blockIdx.x, h = blockIdx.y;
    const int rb = (w < 4) ? w : (11 - w);     // row-block; SMSP pairs balanced

    const size_t blk = (size_t)(b * H + h) * (T * D);
    {
        const int seg = tid & 7;
#pragma unroll
        for (int p = 0; p < 4; p++) {
            const int row = (tid + p * 256) >> 3;          // 0..127
            const uint32_t doff = (uint32_t)(row * 128 + ((seg ^ (row & 7)) << 4));
            const size_t soff = blk + (size_t)row * D + seg * 8;
            cpa16(smb + doff,         g_qhi + soff);
            cpa16(smb + 16384 + doff, g_qlo + soff);
            cpa16(smb + 32768 + doff, g_khi + soff);
            cpa16(smb + 49152 + doff, g_klo + soff);
            cpa16(smb + 65536 + doff, g_vhi + soff);
            cpa16(smb + 81920 + doff, g_vlo + soff);
        }
    }
    CPA_COMMIT();
    CPA_WAIT0();
    __syncthreads();

    const int rA  = (lane & 7) + ((lane >> 3) & 1) * 8;
    const int khA = lane >> 4;
    const int swA = rA & 7;
    const int rB  = (lane & 7) + (lane >> 4) * 8;
    const int khB = (lane >> 3) & 1;
    const int swB = rB & 7;

    const uint32_t aQhi = smb + (uint32_t)((rb * 16 + rA) * 128);
    const uint32_t aQlo = aQhi + 16384;

    // ---------------- S = Q @ K^T (3-split, causal block-skip) ----------------
    float S[16][4];
#pragma unroll
    for (int i = 0; i < 16; i++)
#pragma unroll
        for (int e = 0; e < 4; e++) S[i][e] = 0.f;

#pragma unroll
    for (int ks = 0; ks < 4; ks++) {
        uint32_t qh[4], ql[4];
        const uint32_t aoff = (uint32_t)(((ks * 2 + khA) ^ swA) << 4);
        ldsm4(qh, aQhi + aoff);
        ldsm4(ql, aQlo + aoff);
        const uint32_t boff = (uint32_t)(((ks * 2 + khB) ^ swB) << 4);
#pragma unroll
        for (int g = 0; g < 8; g += 2) {
            if (g > rb) break;
            uint32_t kh0[4], kl0[4];
            const uint32_t bb0 = smb + 32768 + (uint32_t)((g * 16 + rB) * 128);
            ldsm4(kh0, bb0 + boff);
            // start MMAs as soon as the first K fragment lands
            mma16816(S[2 * g],     qh, &kh0[0]);
            ldsm4(kl0, bb0 + 16384 + boff);
            mma16816(S[2 * g + 1], qh, &kh0[2]);
            const bool g1ok = (g + 1) <= rb;
            uint32_t kh1[4], kl1[4];
            if (g1ok) {
                const uint32_t bb1 = smb + 32768 + (uint32_t)(((g + 1) * 16 + rB) * 128);
                ldsm4(kh1, bb1 + boff);
                ldsm4(kl1, bb1 + 16384 + boff);
            }
            mma16816(S[2 * g],     qh, &kl0[0]);
            mma16816(S[2 * g + 1], qh, &kl0[2]);
            mma16816(S[2 * g],     ql, &kh0[0]);
            mma16816(S[2 * g + 1], ql, &kh0[2]);
            if (g1ok) {
                mma16816(S[2 * g + 2], qh, &kh1[0]);
                mma16816(S[2 * g + 3], qh, &kh1[2]);
                mma16816(S[2 * g + 2], qh, &kl1[0]);
                mma16816(S[2 * g + 3], qh, &kl1[2]);
                mma16816(S[2 * g + 2], ql, &kh1[0]);
                mma16816(S[2 * g + 3], ql, &kh1[2]);
            }
        }
    }

    // ---------------- softmax exponentials (q already scaled by D^-1/2) ----------
    const int row0 = rb * 16 + (lane >> 2);
    const int row1 = row0 + 8;
    const int colb = 2 * (lane & 3);
    float sum0 = 0.f, sum1 = 0.f;
#pragma unroll
    for (int nf = 0; nf < 16; nf++) {
        if (nf > 2 * rb + 1) break;
        const int c0 = nf * 8 + colb, c1 = c0 + 1;
        float e00 = (c0 <= row0) ? __expf(S[nf][0]) : 0.f;
        float e01 = (c1 <= row0) ? __expf(S[nf][1]) : 0.f;
        float e10 = (c0 <= row1) ? __expf(S[nf][2]) : 0.f;
        float e11 = (c1 <= row1) ? __expf(S[nf][3]) : 0.f;
        S[nf][0] = e00; S[nf][1] = e01; S[nf][2] = e10; S[nf][3] = e11;
        sum0 += e00 + e01;
        sum1 += e10 + e11;
    }
    sum0 += __shfl_xor_sync(0xFFFFFFFFu, sum0, 1);
    sum0 += __shfl_xor_sync(0xFFFFFFFFu, sum0, 2);
    sum1 += __shfl_xor_sync(0xFFFFFFFFu, sum1, 1);
    sum1 += __shfl_xor_sync(0xFFFFFFFFu, sum1, 2);
    const float inv0 = 1.0f / sum0;
    const float inv1 = 1.0f / sum1;

    // ---------------- O = (raw P) @ V; normalization applied in epilogue --------
    float O[8][4];
#pragma unroll
    for (int i = 0; i < 8; i++)
#pragma unroll
        for (int e = 0; e < 4; e++) O[i][e] = 0.f;

    const int mT = lane >> 3;
    const int rT = lane & 7;

#pragma unroll
    for (int ks = 0; ks < 8; ks++) {
        if (ks > rb) break;
        const int srow = ks * 16 + (mT & 1) * 8 + rT;
        const uint32_t rowOff = (uint32_t)(srow * 128);
        // kick off first V loads before building P
        uint32_t vh[4][4], vl[4][4];
        {
            const int dseg0 = 0 * 2 + (mT >> 1);
            const uint32_t a0 = rowOff + (uint32_t)(((dseg0 ^ (srow & 7)) << 4));
            ldsm4t(vh[0], smb + 65536 + a0);
            ldsm4t(vl[0], smb + 81920 + a0);
        }
        uint32_t phi[4], plo[4];
        hilo_pair(S[2 * ks][0],     S[2 * ks][1],     phi[0], plo[0]);
        hilo_pair(S[2 * ks][2],     S[2 * ks][3],     phi[1], plo[1]);
        hilo_pair(S[2 * ks + 1][0], S[2 * ks + 1][1], phi[2], plo[2]);
        hilo_pair(S[2 * ks + 1][2], S[2 * ks + 1][3], phi[3], plo[3]);
#pragma unroll
        for (int g = 1; g < 4; g++) {
            const int dseg = g * 2 + (mT >> 1);
            const uint32_t addr = rowOff + (uint32_t)(((dseg ^ (srow & 7)) << 4));
            ldsm4t(vh[g], smb + 65536 + addr);
            mma16816(O[2 * (g - 1)],     phi, &vh[g - 1][0]);
            mma16816(O[2 * (g - 1) + 1], phi, &vh[g - 1][2]);
            ldsm4t(vl[g], smb + 81920 + addr);
            mma16816(O[2 * (g - 1)],     phi, &vl[g - 1][0]);
            mma16816(O[2 * (g - 1) + 1], phi, &vl[g - 1][2]);
        }
        mma16816(O[6], phi, &vh[3][0]);
        mma16816(O[7], phi, &vh[3][2]);
        mma16816(O[6], phi, &vl[3][0]);
        mma16816(O[7], phi, &vl[3][2]);
#pragma unroll
        for (int g = 0; g < 4; g++) {
            mma16816(O[2 * g],     plo, &vh[g][0]);
            mma16816(O[2 * g + 1], plo, &vh[g][2]);
        }
    }

    // ---------------- epilogue: normalize, att bf16 hi/lo [b][t][h*64+d] ---------
    const size_t obase = (size_t)b * T * HD + h * D;
#pragma unroll
    for (int nf = 0; nf < 8; nf++) {
        const int d0 = nf * 8 + colb;
        uint32_t hi, lo;
        hilo_pair(O[nf][0] * inv0, O[nf][1] * inv0, hi, lo);
        *(uint32_t*)(g_atthi + obase + (size_t)row0 * HD + d0) = hi;
        *(uint32_t*)(g_attlo + obase + (size_t)row0 * HD + d0) = lo;
        hilo_pair(O[nf][2] * inv1, O[nf][3] * inv1, hi, lo);
        *(uint32_t*)(g_atthi + obase + (size_t)row1 * HD + d0) = hi;
        *(uint32_t*)(g_attlo + obase + (size_t)row1 * HD + d0) = lo;
    }
}

// =================================================================================
extern "C" void kernel_launch(void* const* d_in, const int* in_sizes, int n_in,
                              void* d_out, int out_size)
{
    (void)in_sizes; (void)n_in; (void)out_size;
    const float* x  = (const float*)d_in[0];
    const float* Wq = (const float*)d_in[1];
    const float* Wk = (const float*)d_in[2];
    const float* Wv = (const float*)d_in[3];
    const float* Wp = (const float*)d_in[4];
    const float* bp = (const float*)d_in[5];
    float* out = (float*)d_out;

    cudaFuncSetAttribute(mma_gemm<false>, cudaFuncAttributeMaxDynamicSharedMemorySize, GEMM_SMEM);
    cudaFuncSetAttribute(mma_gemm<true>,  cudaFuncAttributeMaxDynamicSharedMemorySize, GEMM_SMEM);
    cudaFuncSetAttribute(attn_mma, cudaFuncAttributeMaxDynamicSharedMemorySize, ATTN_SMEM);

    conv_x_kernel<<<(BATCH * T * C / 4) / 256, 256>>>(x);
    conv_w_kernel<<<(NQKV * C + 255) / 256, 256>>>(Wq, Wk, Wv);
    conv_wp_kernel<<<(HD * C + 255) / 256, 256>>>(Wp);

    mma_gemm<false><<<dim3(18, BATCH), 256, GEMM_SMEM>>>(nullptr, nullptr);
    attn_mma<<<dim3(BATCH, H), 256, ATTN_SMEM>>>();
    mma_gemm<true><<<dim3(6, BATCH), 256, GEMM_SMEM>>>(bp, out);
}

// round 8
// speedup vs baseline: 1.2445x; 1.2445x over previous
#include <cuda_runtime.h>
#include <cuda_bf16.h>
#include <cuda_fp16.h>
#include <cstdint>

#define BATCH 512
#define T 128
#define C 384
#define H 6
#define D 64
#define HD 384
#define NQKV 1152

typedef unsigned long long ull;

// ---------------- scratch (device globals; no runtime allocation) ----------------
// x and att: fp16 hi/lo (2-term split). Weights: fp16 hi only.
__device__ __align__(256) __half g_xhi[(size_t)BATCH * T * C];
__device__ __align__(256) __half g_xlo[(size_t)BATCH * T * C];
__device__ __align__(256) __half g_wthi[(size_t)NQKV * C];    // [n][k]
__device__ __align__(256) __half g_wpthi[(size_t)HD * C];     // [n][k] = Wp[k][n]
__device__ __align__(256) __half g_atthi[(size_t)BATCH * T * HD];
__device__ __align__(256) __half g_attlo[(size_t)BATCH * T * HD];
// q,k,v [b][h][t][d] bf16 hi/lo (attention stays 3-split bf16; q pre-scaled D^-1/2)
__device__ __align__(256) __nv_bfloat16 g_qhi[(size_t)BATCH * H * T * D];
__device__ __align__(256) __nv_bfloat16 g_qlo[(size_t)BATCH * H * T * D];
__device__ __align__(256) __nv_bfloat16 g_khi[(size_t)BATCH * H * T * D];
__device__ __align__(256) __nv_bfloat16 g_klo[(size_t)BATCH * H * T * D];
__device__ __align__(256) __nv_bfloat16 g_vhi[(size_t)BATCH * H * T * D];
__device__ __align__(256) __nv_bfloat16 g_vlo[(size_t)BATCH * H * T * D];

// ---------------- helpers (baseline PTX, compute_103-safe) ----------------
__device__ __forceinline__ uint32_t smem_u32(const void* p) {
    uint32_t a;
    asm("{ .reg .u64 t; cvta.to.shared.u64 t, %1; cvt.u32.u64 %0, t; }" : "=r"(a) : "l"(p));
    return a;
}
__device__ __forceinline__ void ldsm4(uint32_t* r, uint32_t addr) {
    asm volatile("ldmatrix.sync.aligned.m8n8.x4.shared.b16 {%0,%1,%2,%3}, [%4];"
        : "=r"(r[0]), "=r"(r[1]), "=r"(r[2]), "=r"(r[3]) : "r"(addr));
}
__device__ __forceinline__ void ldsm4t(uint32_t* r, uint32_t addr) {
    asm volatile("ldmatrix.sync.aligned.m8n8.x4.trans.shared.b16 {%0,%1,%2,%3}, [%4];"
        : "=r"(r[0]), "=r"(r[1]), "=r"(r[2]), "=r"(r[3]) : "r"(addr));
}
// bf16 MMA (attention)
__device__ __forceinline__ void mma16816(float* c, const uint32_t* a, const uint32_t* b) {
    asm volatile("mma.sync.aligned.m16n8k16.row.col.f32.bf16.bf16.f32 "
        "{%0,%1,%2,%3}, {%4,%5,%6,%7}, {%8,%9}, {%0,%1,%2,%3};"
        : "+f"(c[0]), "+f"(c[1]), "+f"(c[2]), "+f"(c[3])
        : "r"(a[0]), "r"(a[1]), "r"(a[2]), "r"(a[3]), "r"(b[0]), "r"(b[1]));
}
// fp16 MMA (projection GEMMs)
__device__ __forceinline__ void mma16816f(float* c, const uint32_t* a, const uint32_t* b) {
    asm volatile("mma.sync.aligned.m16n8k16.row.col.f32.f16.f16.f32 "
        "{%0,%1,%2,%3}, {%4,%5,%6,%7}, {%8,%9}, {%0,%1,%2,%3};"
        : "+f"(c[0]), "+f"(c[1]), "+f"(c[2]), "+f"(c[3])
        : "r"(a[0]), "r"(a[1]), "r"(a[2]), "r"(a[3]), "r"(b[0]), "r"(b[1]));
}
__device__ __forceinline__ void cpa16(uint32_t dst, const void* src) {
    asm volatile("cp.async.cg.shared.global [%0], [%1], 16;" :: "r"(dst), "l"(src));
}
#define CPA_COMMIT() asm volatile("cp.async.commit_group;" ::: "memory")
#define CPA_WAIT1()  asm volatile("cp.async.wait_group 1;" ::: "memory")
#define CPA_WAIT0()  asm volatile("cp.async.wait_group 0;" ::: "memory")

// bf16 hi/lo split helpers
__device__ __forceinline__ uint32_t cvt_bf16x2(float lo, float hi) {
    uint32_t r;
    asm("cvt.rn.bf16x2.f32 %0, %1, %2;" : "=r"(r) : "f"(hi), "f"(lo));
    return r;
}
__device__ __forceinline__ float lo_f(uint32_t u) { return __uint_as_float(u << 16); }
__device__ __forceinline__ float hi_f(uint32_t u) { return __uint_as_float(u & 0xFFFF0000u); }
__device__ __forceinline__ void hilo_pair(float a, float b, uint32_t& h, uint32_t& l) {
    h = cvt_bf16x2(a, b);
    l = cvt_bf16x2(a - lo_f(h), b - hi_f(h));
}
// fp16 hi/lo split helper
__device__ __forceinline__ void hilo_pair_f16(float a, float b, uint32_t& h, uint32_t& l) {
    __half ha = __float2half_rn(a), hb = __float2half_rn(b);
    __half la = __float2half_rn(a - __half2float(ha));
    __half lb = __float2half_rn(b - __half2float(hb));
    h = (uint32_t)__half_as_ushort(ha) | ((uint32_t)__half_as_ushort(hb) << 16);
    l = (uint32_t)__half_as_ushort(la) | ((uint32_t)__half_as_ushort(lb) << 16);
}

// =================================================================================
// Conversion kernels
// =================================================================================
__global__ void conv_x_kernel(const float* __restrict__ x) {
    size_t i = ((size_t)blockIdx.x * 256 + threadIdx.x) * 4;
    float4 v = *(const float4*)(x + i);
    uint32_t h0, l0, h1, l1;
    hilo_pair_f16(v.x, v.y, h0, l0);
    hilo_pair_f16(v.z, v.w, h1, l1);
    *(uint32_t*)(g_xhi + i)     = h0;
    *(uint32_t*)(g_xhi + i + 2) = h1;
    *(uint32_t*)(g_xlo + i)     = l0;
    *(uint32_t*)(g_xlo + i + 2) = l1;
}

__global__ void conv_w_kernel(const float* __restrict__ Wq, const float* __restrict__ Wk,
                              const float* __restrict__ Wv) {
    int idx = blockIdx.x * 256 + threadIdx.x;   // n*C + k
    if (idx >= NQKV * C) return;
    int n = idx / C, k = idx - n * C;
    int which = n / HD, rem = n - which * HD;
    int h = rem >> 6, d = rem & 63;
    const float* W = (which == 0) ? Wq : (which == 1) ? Wk : Wv;
    g_wthi[idx] = __float2half_rn(W[((size_t)h * C + k) * D + d]);
}

__global__ void conv_wp_kernel(const float* __restrict__ Wp) {
    int idx = blockIdx.x * 256 + threadIdx.x;   // n*C + k
    if (idx >= HD * C) return;
    int n = idx / C, k = idx - n * C;
    g_wpthi[idx] = __float2half_rn(Wp[(size_t)k * C + n]);
}

// =================================================================================
// fp16 2-term GEMM: Y[128 x 64] = (Ahi + Alo)[128 x 384] @ Bhi[n][k]^T.
// Stage (40KB): Ahi@0 (16K), Alo@16K (16K), Bhi@32K (8K); double-buffered = 80KB.
// 8 warps as 4(m) x 2(n); warp tile 32x32; 16 MMAs + 6 LDSM.x4 per k-step.
// =================================================================================
#define STAGE_BYTES 40960
#define GEMM_SMEM (2 * STAGE_BYTES)

template <bool PROJ>
__global__ __launch_bounds__(256, 2)
void mma_gemm(const float* __restrict__ bp, float* __restrict__ out)
{
    extern __shared__ __align__(1024) char sm[];
    const uint32_t smb = smem_u32(sm);
    const int tid = threadIdx.x, wid = tid >> 5, lane = tid & 31;
    const int b = blockIdx.y, n0 = blockIdx.x * 64;
    const int wm = (wid >> 1) * 32;     // 0,32,64,96
    const int wn = (wid & 1) * 32;      // 0,32

    const __half* __restrict__ Ahi = (PROJ ? g_atthi : g_xhi) + (size_t)b * T * C;
    const __half* __restrict__ Alo = (PROJ ? g_attlo : g_xlo) + (size_t)b * T * C;
    const __half* __restrict__ Bhi = (PROJ ? g_wpthi : g_wthi) + (size_t)n0 * C;

    const int l_row = tid >> 3;          // 0..31
    const int l_seg = tid & 7;

    auto load_chunk = [&](int c, int s) {
        const int c0 = c * 64;
        const uint32_t sb = smb + s * STAGE_BYTES;
#pragma unroll
        for (int p = 0; p < 4; p++) {
            const int row = l_row + p * 32;
            const uint32_t doff = (uint32_t)(row * 128 + ((l_seg ^ (row & 7)) << 4));
            const size_t soff = (size_t)row * C + c0 + l_seg * 8;
            cpa16(sb + doff,         Ahi + soff);
            cpa16(sb + 16384 + doff, Alo + soff);
        }
#pragma unroll
        for (int p = 0; p < 2; p++) {
            const int row = l_row + p * 32;   // 0..63
            const uint32_t doff = (uint32_t)(row * 128 + ((l_seg ^ (row & 7)) << 4));
            const size_t soff = (size_t)row * C + c0 + l_seg * 8;
            cpa16(sb + 32768 + doff, Bhi + soff);
        }
        CPA_COMMIT();
    };

    float acc[2][4][4];
#pragma unroll
    for (int i = 0; i < 2; i++)
#pragma unroll
        for (int j = 0; j < 4; j++)
#pragma unroll
            for (int e = 0; e < 4; e++) acc[i][j][e] = 0.f;

    const int rA  = (lane & 7) + ((lane >> 3) & 1) * 8;
    const int khA = lane >> 4;
    const int swA = rA & 7;
    const int rB  = (lane & 7) + (lane >> 4) * 8;
    const int khB = (lane >> 3) & 1;
    const int swB = rB & 7;

    load_chunk(0, 0);
    load_chunk(1, 1);

    for (int c = 0; c < 6; c++) {
        if (c == 5) CPA_WAIT0(); else CPA_WAIT1();
        __syncthreads();

        const uint32_t sb = smb + (c & 1) * STAGE_BYTES;
        const uint32_t aBase = sb + (uint32_t)((wm + rA) * 128);
        const uint32_t bBase = sb + 32768 + (uint32_t)((wn + rB) * 128);

#pragma unroll
        for (int ks = 0; ks < 4; ks++) {
            const uint32_t aoff = (uint32_t)(((ks * 2 + khA) ^ swA) << 4);
            const uint32_t boff = (uint32_t)(((ks * 2 + khB) ^ swB) << 4);
            uint32_t ahi[2][4], alo[2][4], bh[2][4];
            ldsm4(ahi[0], aBase + aoff);
            ldsm4(bh[0],  bBase + boff);
            ldsm4(ahi[1], aBase + 2048 + aoff);
            ldsm4(bh[1],  bBase + 2048 + boff);
            // pass 1: hi * hi, with Alo LDSMs hidden under the MMAs
            mma16816f(acc[0][0], ahi[0], &bh[0][0]);
            mma16816f(acc[0][1], ahi[0], &bh[0][2]);
            ldsm4(alo[0], aBase + 16384 + aoff);
            mma16816f(acc[0][2], ahi[0], &bh[1][0]);
            mma16816f(acc[0][3], ahi[0], &bh[1][2]);
            ldsm4(alo[1], aBase + 16384 + 2048 + aoff);
            mma16816f(acc[1][0], ahi[1], &bh[0][0]);
            mma16816f(acc[1][1], ahi[1], &bh[0][2]);
            mma16816f(acc[1][2], ahi[1], &bh[1][0]);
            mma16816f(acc[1][3], ahi[1], &bh[1][2]);
            // pass 2: lo * hi
#pragma unroll
            for (int mf = 0; mf < 2; mf++)
#pragma unroll
                for (int nf = 0; nf < 4; nf++)
                    mma16816f(acc[mf][nf], alo[mf], &bh[nf >> 1][(nf & 1) * 2]);
        }
        __syncthreads();
        if (c + 2 < 6) load_chunk(c + 2, (c & 1));
    }

    // ---------------- epilogue ----------------
    const int qrow = lane >> 2;
    const int qcol = (lane & 3) * 2;

    if (PROJ) {
#pragma unroll
        for (int mf = 0; mf < 2; mf++) {
#pragma unroll
            for (int nf = 0; nf < 4; nf++) {
                const int row = wm + mf * 16 + qrow;
                const int col = n0 + wn + nf * 8 + qcol;
                const float2 bb = *(const float2*)(bp + col);
                float* p0 = out + ((size_t)b * T + row) * HD + col;
                float* p1 = out + ((size_t)b * T + row + 8) * HD + col;
                *(float2*)p0 = make_float2(acc[mf][nf][0] + bb.x, acc[mf][nf][1] + bb.y);
                *(float2*)p1 = make_float2(acc[mf][nf][2] + bb.x, acc[mf][nf][3] + bb.y);
            }
        }
    } else {
        const int which = blockIdx.x / 6;       // 0=q,1=k,2=v
        const int hh = blockIdx.x % 6;
        __nv_bfloat16* bh_ = (which == 0) ? g_qhi : (which == 1) ? g_khi : g_vhi;
        __nv_bfloat16* bl_ = (which == 0) ? g_qlo : (which == 1) ? g_klo : g_vlo;
        const float scale = (which == 0) ? 0.125f : 1.0f;   // q pre-scaled by D^-1/2
        const size_t hb = ((size_t)(b * H + hh) * T) * D;
#pragma unroll
        for (int mf = 0; mf < 2; mf++) {
#pragma unroll
            for (int nf = 0; nf < 4; nf++) {
                const int row = wm + mf * 16 + qrow;
                const int dd = wn + nf * 8 + qcol;
                const size_t o0 = hb + (size_t)row * D + dd;
                uint32_t hi, lo;
                hilo_pair(acc[mf][nf][0] * scale, acc[mf][nf][1] * scale, hi, lo);
                *(uint32_t*)(bh_ + o0) = hi;
                *(uint32_t*)(bl_ + o0) = lo;
                hilo_pair(acc[mf][nf][2] * scale, acc[mf][nf][3] * scale, hi, lo);
                *(uint32_t*)(bh_ + o0 + 8 * D) = hi;
                *(uint32_t*)(bl_ + o0 + 8 * D) = lo;
            }
        }
    }
}

// =================================================================================
// MMA attention per (b, h) — bf16 3-split (unchanged math), emits att fp16 hi/lo.
// =================================================================================
#define ATTN_SMEM 98304

__global__ __launch_bounds__(256, 1)
void attn_mma()
{
    extern __shared__ __align__(1024) char sm[];
    const uint32_t smb = smem_u32(sm);
    const int tid = threadIdx.x, w = tid >> 5, lane = tid & 31;
    const int b = blockIdx.x, h = blockIdx.y;
    const int rb = (w < 4) ? w : (11 - w);     // row-block; SMSP pairs balanced

    const size_t blk = (size_t)(b * H + h) * (T * D);
    {
        const int seg = tid & 7;
#pragma unroll
        for (int p = 0; p < 4; p++) {
            const int row = (tid + p * 256) >> 3;          // 0..127
            const uint32_t doff = (uint32_t)(row * 128 + ((seg ^ (row & 7)) << 4));
            const size_t soff = blk + (size_t)row * D + seg * 8;
            cpa16(smb + doff,         g_qhi + soff);
            cpa16(smb + 16384 + doff, g_qlo + soff);
            cpa16(smb + 32768 + doff, g_khi + soff);
            cpa16(smb + 49152 + doff, g_klo + soff);
            cpa16(smb + 65536 + doff, g_vhi + soff);
            cpa16(smb + 81920 + doff, g_vlo + soff);
        }
    }
    CPA_COMMIT();
    CPA_WAIT0();
    __syncthreads();

    const int rA  = (lane & 7) + ((lane >> 3) & 1) * 8;
    const int khA = lane >> 4;
    const int swA = rA & 7;
    const int rB  = (lane & 7) + (lane >> 4) * 8;
    const int khB = (lane >> 3) & 1;
    const int swB = rB & 7;

    const uint32_t aQhi = smb + (uint32_t)((rb * 16 + rA) * 128);
    const uint32_t aQlo = aQhi + 16384;

    // ---------------- S = Q @ K^T (3-split, causal block-skip) ----------------
    float S[16][4];
#pragma unroll
    for (int i = 0; i < 16; i++)
#pragma unroll
        for (int e = 0; e < 4; e++) S[i][e] = 0.f;

#pragma unroll
    for (int ks = 0; ks < 4; ks++) {
        uint32_t qh[4], ql[4];
        const uint32_t aoff = (uint32_t)(((ks * 2 + khA) ^ swA) << 4);
        ldsm4(qh, aQhi + aoff);
        ldsm4(ql, aQlo + aoff);
        const uint32_t boff = (uint32_t)(((ks * 2 + khB) ^ swB) << 4);
#pragma unroll
        for (int g = 0; g < 8; g += 2) {
            if (g > rb) break;
            uint32_t kh0[4], kl0[4];
            const uint32_t bb0 = smb + 32768 + (uint32_t)((g * 16 + rB) * 128);
            ldsm4(kh0, bb0 + boff);
            mma16816(S[2 * g],     qh, &kh0[0]);
            ldsm4(kl0, bb0 + 16384 + boff);
            mma16816(S[2 * g + 1], qh, &kh0[2]);
            const bool g1ok = (g + 1) <= rb;
            uint32_t kh1[4], kl1[4];
            if (g1ok) {
                const uint32_t bb1 = smb + 32768 + (uint32_t)(((g + 1) * 16 + rB) * 128);
                ldsm4(kh1, bb1 + boff);
                ldsm4(kl1, bb1 + 16384 + boff);
            }
            mma16816(S[2 * g],     qh, &kl0[0]);
            mma16816(S[2 * g + 1], qh, &kl0[2]);
            mma16816(S[2 * g],     ql, &kh0[0]);
            mma16816(S[2 * g + 1], ql, &kh0[2]);
            if (g1ok) {
                mma16816(S[2 * g + 2], qh, &kh1[0]);
                mma16816(S[2 * g + 3], qh, &kh1[2]);
                mma16816(S[2 * g + 2], qh, &kl1[0]);
                mma16816(S[2 * g + 3], qh, &kl1[2]);
                mma16816(S[2 * g + 2], ql, &kh1[0]);
                mma16816(S[2 * g + 3], ql, &kh1[2]);
            }
        }
    }

    // ---------------- softmax exponentials (q already scaled by D^-1/2) ----------
    const int row0 = rb * 16 + (lane >> 2);
    const int row1 = row0 + 8;
    const int colb = 2 * (lane & 3);
    float sum0 = 0.f, sum1 = 0.f;
#pragma unroll
    for (int nf = 0; nf < 16; nf++) {
        if (nf > 2 * rb + 1) break;
        const int c0 = nf * 8 + colb, c1 = c0 + 1;
        float e00 = (c0 <= row0) ? __expf(S[nf][0]) : 0.f;
        float e01 = (c1 <= row0) ? __expf(S[nf][1]) : 0.f;
        float e10 = (c0 <= row1) ? __expf(S[nf][2]) : 0.f;
        float e11 = (c1 <= row1) ? __expf(S[nf][3]) : 0.f;
        S[nf][0] = e00; S[nf][1] = e01; S[nf][2] = e10; S[nf][3] = e11;
        sum0 += e00 + e01;
        sum1 += e10 + e11;
    }
    sum0 += __shfl_xor_sync(0xFFFFFFFFu, sum0, 1);
    sum0 += __shfl_xor_sync(0xFFFFFFFFu, sum0, 2);
    sum1 += __shfl_xor_sync(0xFFFFFFFFu, sum1, 1);
    sum1 += __shfl_xor_sync(0xFFFFFFFFu, sum1, 2);
    const float inv0 = 1.0f / sum0;
    const float inv1 = 1.0f / sum1;

    // ---------------- O = (raw P) @ V; normalization applied in epilogue --------
    float O[8][4];
#pragma unroll
    for (int i = 0; i < 8; i++)
#pragma unroll
        for (int e = 0; e < 4; e++) O[i][e] = 0.f;

    const int mT = lane >> 3;
    const int rT = lane & 7;

#pragma unroll
    for (int ks = 0; ks < 8; ks++) {
        if (ks > rb) break;
        const int srow = ks * 16 + (mT & 1) * 8 + rT;
        const uint32_t rowOff = (uint32_t)(srow * 128);
        uint32_t vh[4][4], vl[4][4];
        {
            const int dseg0 = (mT >> 1);
            const uint32_t a0 = rowOff + (uint32_t)(((dseg0 ^ (srow & 7)) << 4));
            ldsm4t(vh[0], smb + 65536 + a0);
            ldsm4t(vl[0], smb + 81920 + a0);
        }
        uint32_t phi[4], plo[4];
        hilo_pair(S[2 * ks][0],     S[2 * ks][1],     phi[0], plo[0]);
        hilo_pair(S[2 * ks][2],     S[2 * ks][3],     phi[1], plo[1]);
        hilo_pair(S[2 * ks + 1][0], S[2 * ks + 1][1], phi[2], plo[2]);
        hilo_pair(S[2 * ks + 1][2], S[2 * ks + 1][3], phi[3], plo[3]);
#pragma unroll
        for (int g = 1; g < 4; g++) {
            const int dseg = g * 2 + (mT >> 1);
            const uint32_t addr = rowOff + (uint32_t)(((dseg ^ (srow & 7)) << 4));
            ldsm4t(vh[g], smb + 65536 + addr);
            mma16816(O[2 * (g - 1)],     phi, &vh[g - 1][0]);
            mma16816(O[2 * (g - 1) + 1], phi, &vh[g - 1][2]);
            ldsm4t(vl[g], smb + 81920 + addr);
            mma16816(O[2 * (g - 1)],     phi, &vl[g - 1][0]);
            mma16816(O[2 * (g - 1) + 1], phi, &vl[g - 1][2]);
        }
        mma16816(O[6], phi, &vh[3][0]);
        mma16816(O[7], phi, &vh[3][2]);
        mma16816(O[6], phi, &vl[3][0]);
        mma16816(O[7], phi, &vl[3][2]);
#pragma unroll
        for (int g = 0; g < 4; g++) {
            mma16816(O[2 * g],     plo, &vh[g][0]);
            mma16816(O[2 * g + 1], plo, &vh[g][2]);
        }
    }

    // ---------------- epilogue: normalize, att fp16 hi/lo [b][t][h*64+d] ---------
    const size_t obase = (size_t)b * T * HD + h * D;
#pragma unroll
    for (int nf = 0; nf < 8; nf++) {
        const int d0 = nf * 8 + colb;
        uint32_t hi, lo;
        hilo_pair_f16(O[nf][0] * inv0, O[nf][1] * inv0, hi, lo);
        *(uint32_t*)(g_atthi + obase + (size_t)row0 * HD + d0) = hi;
        *(uint32_t*)(g_attlo + obase + (size_t)row0 * HD + d0) = lo;
        hilo_pair_f16(O[nf][2] * inv1, O[nf][3] * inv1, hi, lo);
        *(uint32_t*)(g_atthi + obase + (size_t)row1 * HD + d0) = hi;
        *(uint32_t*)(g_attlo + obase + (size_t)row1 * HD + d0) = lo;
    }
}

// =================================================================================
extern "C" void kernel_launch(void* const* d_in, const int* in_sizes, int n_in,
                              void* d_out, int out_size)
{
    (void)in_sizes; (void)n_in; (void)out_size;
    const float* x  = (const float*)d_in[0];
    const float* Wq = (const float*)d_in[1];
    const float* Wk = (const float*)d_in[2];
    const float* Wv = (const float*)d_in[3];
    const float* Wp = (const float*)d_in[4];
    const float* bp = (const float*)d_in[5];
    float* out = (float*)d_out;

    cudaFuncSetAttribute(mma_gemm<false>, cudaFuncAttributeMaxDynamicSharedMemorySize, GEMM_SMEM);
    cudaFuncSetAttribute(mma_gemm<true>,  cudaFuncAttributeMaxDynamicSharedMemorySize, GEMM_SMEM);
    cudaFuncSetAttribute(attn_mma, cudaFuncAttributeMaxDynamicSharedMemorySize, ATTN_SMEM);

    conv_x_kernel<<<(BATCH * T * C / 4) / 256, 256>>>(x);
    conv_w_kernel<<<(NQKV * C + 255) / 256, 256>>>(Wq, Wk, Wv);
    conv_wp_kernel<<<(HD * C + 255) / 256, 256>>>(Wp);

    mma_gemm<false><<<dim3(18, BATCH), 256, GEMM_SMEM>>>(nullptr, nullptr);
    attn_mma<<<dim3(BATCH, H), 256, ATTN_SMEM>>>();
    mma_gemm<true><<<dim3(6, BATCH), 256, GEMM_SMEM>>>(bp, out);
}

// round 9
// speedup vs baseline: 1.7851x; 1.4344x over previous
#include <cuda_runtime.h>
#include <cuda_bf16.h>
#include <cuda_fp16.h>
#include <cstdint>

#define BATCH 512
#define T 128
#define C 384
#define H 6
#define D 64
#define HD 384
#define NQKV 1152

typedef unsigned long long ull;

// ---------------- scratch (device globals; no runtime allocation) ----------------
// x, att, weights: plain fp16 (single term).
__device__ __align__(256) __half g_xhi[(size_t)BATCH * T * C];
__device__ __align__(256) __half g_wthi[(size_t)NQKV * C];    // [n][k]
__device__ __align__(256) __half g_wpthi[(size_t)HD * C];     // [n][k] = Wp[k][n]
__device__ __align__(256) __half g_atthi[(size_t)BATCH * T * HD];
// q,k,v [b][h][t][d] bf16 hi/lo (attention stays 3-split bf16; q pre-scaled D^-1/2)
__device__ __align__(256) __nv_bfloat16 g_qhi[(size_t)BATCH * H * T * D];
__device__ __align__(256) __nv_bfloat16 g_qlo[(size_t)BATCH * H * T * D];
__device__ __align__(256) __nv_bfloat16 g_khi[(size_t)BATCH * H * T * D];
__device__ __align__(256) __nv_bfloat16 g_klo[(size_t)BATCH * H * T * D];
__device__ __align__(256) __nv_bfloat16 g_vhi[(size_t)BATCH * H * T * D];
__device__ __align__(256) __nv_bfloat16 g_vlo[(size_t)BATCH * H * T * D];

// ---------------- helpers (baseline PTX, compute_103-safe) ----------------
__device__ __forceinline__ uint32_t smem_u32(const void* p) {
    uint32_t a;
    asm("{ .reg .u64 t; cvta.to.shared.u64 t, %1; cvt.u32.u64 %0, t; }" : "=r"(a) : "l"(p));
    return a;
}
__device__ __forceinline__ void ldsm4(uint32_t* r, uint32_t addr) {
    asm volatile("ldmatrix.sync.aligned.m8n8.x4.shared.b16 {%0,%1,%2,%3}, [%4];"
        : "=r"(r[0]), "=r"(r[1]), "=r"(r[2]), "=r"(r[3]) : "r"(addr));
}
__device__ __forceinline__ void ldsm4t(uint32_t* r, uint32_t addr) {
    asm volatile("ldmatrix.sync.aligned.m8n8.x4.trans.shared.b16 {%0,%1,%2,%3}, [%4];"
        : "=r"(r[0]), "=r"(r[1]), "=r"(r[2]), "=r"(r[3]) : "r"(addr));
}
// bf16 MMA (attention)
__device__ __forceinline__ void mma16816(float* c, const uint32_t* a, const uint32_t* b) {
    asm volatile("mma.sync.aligned.m16n8k16.row.col.f32.bf16.bf16.f32 "
        "{%0,%1,%2,%3}, {%4,%5,%6,%7}, {%8,%9}, {%0,%1,%2,%3};"
        : "+f"(c[0]), "+f"(c[1]), "+f"(c[2]), "+f"(c[3])
        : "r"(a[0]), "r"(a[1]), "r"(a[2]), "r"(a[3]), "r"(b[0]), "r"(b[1]));
}
// fp16 MMA (projection GEMMs)
__device__ __forceinline__ void mma16816f(float* c, const uint32_t* a, const uint32_t* b) {
    asm volatile("mma.sync.aligned.m16n8k16.row.col.f32.f16.f16.f32 "
        "{%0,%1,%2,%3}, {%4,%5,%6,%7}, {%8,%9}, {%0,%1,%2,%3};"
        : "+f"(c[0]), "+f"(c[1]), "+f"(c[2]), "+f"(c[3])
        : "r"(a[0]), "r"(a[1]), "r"(a[2]), "r"(a[3]), "r"(b[0]), "r"(b[1]));
}
__device__ __forceinline__ void cpa16(uint32_t dst, const void* src) {
    asm volatile("cp.async.cg.shared.global [%0], [%1], 16;" :: "r"(dst), "l"(src));
}
#define CPA_COMMIT() asm volatile("cp.async.commit_group;" ::: "memory")
#define CPA_WAIT1()  asm volatile("cp.async.wait_group 1;" ::: "memory")
#define CPA_WAIT0()  asm volatile("cp.async.wait_group 0;" ::: "memory")

// bf16 hi/lo split helpers (attention inputs)
__device__ __forceinline__ uint32_t cvt_bf16x2(float lo, float hi) {
    uint32_t r;
    asm("cvt.rn.bf16x2.f32 %0, %1, %2;" : "=r"(r) : "f"(hi), "f"(lo));
    return r;
}
__device__ __forceinline__ float lo_f(uint32_t u) { return __uint_as_float(u << 16); }
__device__ __forceinline__ float hi_f(uint32_t u) { return __uint_as_float(u & 0xFFFF0000u); }
__device__ __forceinline__ void hilo_pair(float a, float b, uint32_t& h, uint32_t& l) {
    h = cvt_bf16x2(a, b);
    l = cvt_bf16x2(a - lo_f(h), b - hi_f(h));
}
__device__ __forceinline__ uint32_t pack_f16x2(float a, float b) {
    __half2 h = __floats2half2_rn(a, b);
    return *(uint32_t*)&h;
}

// =================================================================================
// Conversion kernels
// =================================================================================
__global__ void conv_x_kernel(const float* __restrict__ x) {
    size_t i = ((size_t)blockIdx.x * 256 + threadIdx.x) * 4;
    float4 v = *(const float4*)(x + i);
    *(uint32_t*)(g_xhi + i)     = pack_f16x2(v.x, v.y);
    *(uint32_t*)(g_xhi + i + 2) = pack_f16x2(v.z, v.w);
}

__global__ void conv_w_kernel(const float* __restrict__ Wq, const float* __restrict__ Wk,
                              const float* __restrict__ Wv) {
    int idx = blockIdx.x * 256 + threadIdx.x;   // n*C + k
    if (idx >= NQKV * C) return;
    int n = idx / C, k = idx - n * C;
    int which = n / HD, rem = n - which * HD;
    int h = rem >> 6, d = rem & 63;
    const float* W = (which == 0) ? Wq : (which == 1) ? Wk : Wv;
    g_wthi[idx] = __float2half_rn(W[((size_t)h * C + k) * D + d]);
}

__global__ void conv_wp_kernel(const float* __restrict__ Wp) {
    int idx = blockIdx.x * 256 + threadIdx.x;   // n*C + k
    if (idx >= HD * C) return;
    int n = idx / C, k = idx - n * C;
    g_wpthi[idx] = __float2half_rn(Wp[(size_t)k * C + n]);
}

// =================================================================================
// Pure fp16 GEMM: Y[128 x 64] = A[128 x 384] @ B[n][k]^T.
// Stage (24KB): A@0 (16K), B@16K (8K); double-buffered = 48KB; 3 CTAs/SM.
// 8 warps as 4(m) x 2(n); warp tile 32x32; 8 MMAs + 4 LDSM.x4 per k-step.
// =================================================================================
#define STAGE_BYTES 24576
#define GEMM_SMEM (2 * STAGE_BYTES)

template <bool PROJ>
__global__ __launch_bounds__(256, 3)
void mma_gemm(const float* __restrict__ bp, float* __restrict__ out)
{
    extern __shared__ __align__(1024) char sm[];
    const uint32_t smb = smem_u32(sm);
    const int tid = threadIdx.x, wid = tid >> 5, lane = tid & 31;
    const int b = blockIdx.y, n0 = blockIdx.x * 64;
    const int wm = (wid >> 1) * 32;     // 0,32,64,96
    const int wn = (wid & 1) * 32;      // 0,32

    const __half* __restrict__ Ahi = (PROJ ? g_atthi : g_xhi) + (size_t)b * T * C;
    const __half* __restrict__ Bhi = (PROJ ? g_wpthi : g_wthi) + (size_t)n0 * C;

    const int l_row = tid >> 3;          // 0..31
    const int l_seg = tid & 7;

    auto load_chunk = [&](int c, int s) {
        const int c0 = c * 64;
        const uint32_t sb = smb + s * STAGE_BYTES;
#pragma unroll
        for (int p = 0; p < 4; p++) {
            const int row = l_row + p * 32;
            const uint32_t doff = (uint32_t)(row * 128 + ((l_seg ^ (row & 7)) << 4));
            cpa16(sb + doff, Ahi + (size_t)row * C + c0 + l_seg * 8);
        }
#pragma unroll
        for (int p = 0; p < 2; p++) {
            const int row = l_row + p * 32;   // 0..63
            const uint32_t doff = (uint32_t)(row * 128 + ((l_seg ^ (row & 7)) << 4));
            cpa16(sb + 16384 + doff, Bhi + (size_t)row * C + c0 + l_seg * 8);
        }
        CPA_COMMIT();
    };

    float acc[2][4][4];
#pragma unroll
    for (int i = 0; i < 2; i++)
#pragma unroll
        for (int j = 0; j < 4; j++)
#pragma unroll
            for (int e = 0; e < 4; e++) acc[i][j][e] = 0.f;

    const int rA  = (lane & 7) + ((lane >> 3) & 1) * 8;
    const int khA = lane >> 4;
    const int swA = rA & 7;
    const int rB  = (lane & 7) + (lane >> 4) * 8;
    const int khB = (lane >> 3) & 1;
    const int swB = rB & 7;

    load_chunk(0, 0);
    load_chunk(1, 1);

    for (int c = 0; c < 6; c++) {
        if (c == 5) CPA_WAIT0(); else CPA_WAIT1();
        __syncthreads();

        const uint32_t sb = smb + (c & 1) * STAGE_BYTES;
        const uint32_t aBase = sb + (uint32_t)((wm + rA) * 128);
        const uint32_t bBase = sb + 16384 + (uint32_t)((wn + rB) * 128);

#pragma unroll
        for (int ks = 0; ks < 4; ks++) {
            const uint32_t aoff = (uint32_t)(((ks * 2 + khA) ^ swA) << 4);
            const uint32_t boff = (uint32_t)(((ks * 2 + khB) ^ swB) << 4);
            uint32_t ahi[2][4], bh[2][4];
            ldsm4(ahi[0], aBase + aoff);
            ldsm4(bh[0],  bBase + boff);
            ldsm4(ahi[1], aBase + 2048 + aoff);
            ldsm4(bh[1],  bBase + 2048 + boff);
            mma16816f(acc[0][0], ahi[0], &bh[0][0]);
            mma16816f(acc[0][1], ahi[0], &bh[0][2]);
            mma16816f(acc[0][2], ahi[0], &bh[1][0]);
            mma16816f(acc[0][3], ahi[0], &bh[1][2]);
            mma16816f(acc[1][0], ahi[1], &bh[0][0]);
            mma16816f(acc[1][1], ahi[1], &bh[0][2]);
            mma16816f(acc[1][2], ahi[1], &bh[1][0]);
            mma16816f(acc[1][3], ahi[1], &bh[1][2]);
        }
        __syncthreads();
        if (c + 2 < 6) load_chunk(c + 2, (c & 1));
    }

    // ---------------- epilogue ----------------
    const int qrow = lane >> 2;
    const int qcol = (lane & 3) * 2;

    if (PROJ) {
#pragma unroll
        for (int mf = 0; mf < 2; mf++) {
#pragma unroll
            for (int nf = 0; nf < 4; nf++) {
                const int row = wm + mf * 16 + qrow;
                const int col = n0 + wn + nf * 8 + qcol;
                const float2 bb = *(const float2*)(bp + col);
                float* p0 = out + ((size_t)b * T + row) * HD + col;
                float* p1 = out + ((size_t)b * T + row + 8) * HD + col;
                *(float2*)p0 = make_float2(acc[mf][nf][0] + bb.x, acc[mf][nf][1] + bb.y);
                *(float2*)p1 = make_float2(acc[mf][nf][2] + bb.x, acc[mf][nf][3] + bb.y);
            }
        }
    } else {
        const int which = blockIdx.x / 6;       // 0=q,1=k,2=v
        const int hh = blockIdx.x % 6;
        __nv_bfloat16* bh_ = (which == 0) ? g_qhi : (which == 1) ? g_khi : g_vhi;
        __nv_bfloat16* bl_ = (which == 0) ? g_qlo : (which == 1) ? g_klo : g_vlo;
        const float scale = (which == 0) ? 0.125f : 1.0f;   // q pre-scaled by D^-1/2
        const size_t hb = ((size_t)(b * H + hh) * T) * D;
#pragma unroll
        for (int mf = 0; mf < 2; mf++) {
#pragma unroll
            for (int nf = 0; nf < 4; nf++) {
                const int row = wm + mf * 16 + qrow;
                const int dd = wn + nf * 8 + qcol;
                const size_t o0 = hb + (size_t)row * D + dd;
                uint32_t hi, lo;
                hilo_pair(acc[mf][nf][0] * scale, acc[mf][nf][1] * scale, hi, lo);
                *(uint32_t*)(bh_ + o0) = hi;
                *(uint32_t*)(bl_ + o0) = lo;
                hilo_pair(acc[mf][nf][2] * scale, acc[mf][nf][3] * scale, hi, lo);
                *(uint32_t*)(bh_ + o0 + 8 * D) = hi;
                *(uint32_t*)(bl_ + o0 + 8 * D) = lo;
            }
        }
    }
}

// =================================================================================
// MMA attention per (b, h) — bf16 3-split (unchanged math), emits att fp16.
// =================================================================================
#define ATTN_SMEM 98304

__global__ __launch_bounds__(256, 1)
void attn_mma()
{
    extern __shared__ __align__(1024) char sm[];
    const uint32_t smb = smem_u32(sm);
    const int tid = threadIdx.x, w = tid >> 5, lane = tid & 31;
    const int b = blockIdx.x, h = blockIdx.y;
    const int rb = (w < 4) ? w : (11 - w);     // row-block; SMSP pairs balanced

    const size_t blk = (size_t)(b * H + h) * (T * D);
    {
        const int seg = tid & 7;
#pragma unroll
        for (int p = 0; p < 4; p++) {
            const int row = (tid + p * 256) >> 3;          // 0..127
            const uint32_t doff = (uint32_t)(row * 128 + ((seg ^ (row & 7)) << 4));
            const size_t soff = blk + (size_t)row * D + seg * 8;
            cpa16(smb + doff,         g_qhi + soff);
            cpa16(smb + 16384 + doff, g_qlo + soff);
            cpa16(smb + 32768 + doff, g_khi + soff);
            cpa16(smb + 49152 + doff, g_klo + soff);
            cpa16(smb + 65536 + doff, g_vhi + soff);
            cpa16(smb + 81920 + doff, g_vlo + soff);
        }
    }
    CPA_COMMIT();
    CPA_WAIT0();
    __syncthreads();

    const int rA  = (lane & 7) + ((lane >> 3) & 1) * 8;
    const int khA = lane >> 4;
    const int swA = rA & 7;
    const int rB  = (lane & 7) + (lane >> 4) * 8;
    const int khB = (lane >> 3) & 1;
    const int swB = rB & 7;

    const uint32_t aQhi = smb + (uint32_t)((rb * 16 + rA) * 128);
    const uint32_t aQlo = aQhi + 16384;

    // ---------------- S = Q @ K^T (3-split, causal block-skip) ----------------
    float S[16][4];
#pragma unroll
    for (int i = 0; i < 16; i++)
#pragma unroll
        for (int e = 0; e < 4; e++) S[i][e] = 0.f;

#pragma unroll
    for (int ks = 0; ks < 4; ks++) {
        uint32_t qh[4], ql[4];
        const uint32_t aoff = (uint32_t)(((ks * 2 + khA) ^ swA) << 4);
        ldsm4(qh, aQhi + aoff);
        ldsm4(ql, aQlo + aoff);
        const uint32_t boff = (uint32_t)(((ks * 2 + khB) ^ swB) << 4);
#pragma unroll
        for (int g = 0; g < 8; g += 2) {
            if (g > rb) break;
            uint32_t kh0[4], kl0[4];
            const uint32_t bb0 = smb + 32768 + (uint32_t)((g * 16 + rB) * 128);
            ldsm4(kh0, bb0 + boff);
            mma16816(S[2 * g],     qh, &kh0[0]);
            ldsm4(kl0, bb0 + 16384 + boff);
            mma16816(S[2 * g + 1], qh, &kh0[2]);
            const bool g1ok = (g + 1) <= rb;
            uint32_t kh1[4], kl1[4];
            if (g1ok) {
                const uint32_t bb1 = smb + 32768 + (uint32_t)(((g + 1) * 16 + rB) * 128);
                ldsm4(kh1, bb1 + boff);
                ldsm4(kl1, bb1 + 16384 + boff);
            }
            mma16816(S[2 * g],     qh, &kl0[0]);
            mma16816(S[2 * g + 1], qh, &kl0[2]);
            mma16816(S[2 * g],     ql, &kh0[0]);
            mma16816(S[2 * g + 1], ql, &kh0[2]);
            if (g1ok) {
                mma16816(S[2 * g + 2], qh, &kh1[0]);
                mma16816(S[2 * g + 3], qh, &kh1[2]);
                mma16816(S[2 * g + 2], qh, &kl1[0]);
                mma16816(S[2 * g + 3], qh, &kl1[2]);
                mma16816(S[2 * g + 2], ql, &kh1[0]);
                mma16816(S[2 * g + 3], ql, &kh1[2]);
            }
        }
    }

    // ---------------- softmax exponentials (q already scaled by D^-1/2) ----------
    const int row0 = rb * 16 + (lane >> 2);
    const int row1 = row0 + 8;
    const int colb = 2 * (lane & 3);
    float sum0 = 0.f, sum1 = 0.f;
#pragma unroll
    for (int nf = 0; nf < 16; nf++) {
        if (nf > 2 * rb + 1) break;
        const int c0 = nf * 8 + colb, c1 = c0 + 1;
        float e00 = (c0 <= row0) ? __expf(S[nf][0]) : 0.f;
        float e01 = (c1 <= row0) ? __expf(S[nf][1]) : 0.f;
        float e10 = (c0 <= row1) ? __expf(S[nf][2]) : 0.f;
        float e11 = (c1 <= row1) ? __expf(S[nf][3]) : 0.f;
        S[nf][0] = e00; S[nf][1] = e01; S[nf][2] = e10; S[nf][3] = e11;
        sum0 += e00 + e01;
        sum1 += e10 + e11;
    }
    sum0 += __shfl_xor_sync(0xFFFFFFFFu, sum0, 1);
    sum0 += __shfl_xor_sync(0xFFFFFFFFu, sum0, 2);
    sum1 += __shfl_xor_sync(0xFFFFFFFFu, sum1, 1);
    sum1 += __shfl_xor_sync(0xFFFFFFFFu, sum1, 2);
    const float inv0 = 1.0f / sum0;
    const float inv1 = 1.0f / sum1;

    // ---------------- O = (raw P) @ V; normalization applied in epilogue --------
    float O[8][4];
#pragma unroll
    for (int i = 0; i < 8; i++)
#pragma unroll
        for (int e = 0; e < 4; e++) O[i][e] = 0.f;

    const int mT = lane >> 3;
    const int rT = lane & 7;

#pragma unroll
    for (int ks = 0; ks < 8; ks++) {
        if (ks > rb) break;
        const int srow = ks * 16 + (mT & 1) * 8 + rT;
        const uint32_t rowOff = (uint32_t)(srow * 128);
        uint32_t vh[4][4], vl[4][4];
        {
            const int dseg0 = (mT >> 1);
            const uint32_t a0 = rowOff + (uint32_t)(((dseg0 ^ (srow & 7)) << 4));
            ldsm4t(vh[0], smb + 65536 + a0);
            ldsm4t(vl[0], smb + 81920 + a0);
        }
        uint32_t phi[4], plo[4];
        hilo_pair(S[2 * ks][0],     S[2 * ks][1],     phi[0], plo[0]);
        hilo_pair(S[2 * ks][2],     S[2 * ks][3],     phi[1], plo[1]);
        hilo_pair(S[2 * ks + 1][0], S[2 * ks + 1][1], phi[2], plo[2]);
        hilo_pair(S[2 * ks + 1][2], S[2 * ks + 1][3], phi[3], plo[3]);
#pragma unroll
        for (int g = 1; g < 4; g++) {
            const int dseg = g * 2 + (mT >> 1);
            const uint32_t addr = rowOff + (uint32_t)(((dseg ^ (srow & 7)) << 4));
            ldsm4t(vh[g], smb + 65536 + addr);
            mma16816(O[2 * (g - 1)],     phi, &vh[g - 1][0]);
            mma16816(O[2 * (g - 1) + 1], phi, &vh[g - 1][2]);
            ldsm4t(vl[g], smb + 81920 + addr);
            mma16816(O[2 * (g - 1)],     phi, &vl[g - 1][0]);
            mma16816(O[2 * (g - 1) + 1], phi, &vl[g - 1][2]);
        }
        mma16816(O[6], phi, &vh[3][0]);
        mma16816(O[7], phi, &vh[3][2]);
        mma16816(O[6], phi, &vl[3][0]);
        mma16816(O[7], phi, &vl[3][2]);
#pragma unroll
        for (int g = 0; g < 4; g++) {
            mma16816(O[2 * g],     plo, &vh[g][0]);
            mma16816(O[2 * g + 1], plo, &vh[g][2]);
        }
    }

    // ---------------- epilogue: normalize, att fp16 [b][t][h*64+d] ---------
    const size_t obase = (size_t)b * T * HD + h * D;
#pragma unroll
    for (int nf = 0; nf < 8; nf++) {
        const int d0 = nf * 8 + colb;
        *(uint32_t*)(g_atthi + obase + (size_t)row0 * HD + d0) =
            pack_f16x2(O[nf][0] * inv0, O[nf][1] * inv0);
        *(uint32_t*)(g_atthi + obase + (size_t)row1 * HD + d0) =
            pack_f16x2(O[nf][2] * inv1, O[nf][3] * inv1);
    }
}

// =================================================================================
extern "C" void kernel_launch(void* const* d_in, const int* in_sizes, int n_in,
                              void* d_out, int out_size)
{
    (void)in_sizes; (void)n_in; (void)out_size;
    const float* x  = (const float*)d_in[0];
    const float* Wq = (const float*)d_in[1];
    const float* Wk = (const float*)d_in[2];
    const float* Wv = (const float*)d_in[3];
    const float* Wp = (const float*)d_in[4];
    const float* bp = (const float*)d_in[5];
    float* out = (float*)d_out;

    cudaFuncSetAttribute(mma_gemm<false>, cudaFuncAttributeMaxDynamicSharedMemorySize, GEMM_SMEM);
    cudaFuncSetAttribute(mma_gemm<true>,  cudaFuncAttributeMaxDynamicSharedMemorySize, GEMM_SMEM);
    cudaFuncSetAttribute(attn_mma, cudaFuncAttributeMaxDynamicSharedMemorySize, ATTN_SMEM);

    conv_x_kernel<<<(BATCH * T * C / 4) / 256, 256>>>(x);
    conv_w_kernel<<<(NQKV * C + 255) / 256, 256>>>(Wq, Wk, Wv);
    conv_wp_kernel<<<(HD * C + 255) / 256, 256>>>(Wp);

    mma_gemm<false><<<dim3(18, BATCH), 256, GEMM_SMEM>>>(nullptr, nullptr);
    attn_mma<<<dim3(BATCH, H), 256, ATTN_SMEM>>>();
    mma_gemm<true><<<dim3(6, BATCH), 256, GEMM_SMEM>>>(bp, out);
}

// round 10
// speedup vs baseline: 1.7919x; 1.0038x over previous
#include <cuda_runtime.h>
#include <cuda_bf16.h>
#include <cuda_fp16.h>
#include <cstdint>

#define BATCH 512
#define T 128
#define C 384
#define H 6
#define D 64
#define HD 384
#define NQKV 1152

typedef unsigned long long ull;

// ---------------- scratch (device globals; no runtime allocation) ----------------
// x, att, weights: plain fp16 (single term).
__device__ __align__(256) __half g_xhi[(size_t)BATCH * T * C];
__device__ __align__(256) __half g_wthi[(size_t)NQKV * C];    // [n][k]
__device__ __align__(256) __half g_wpthi[(size_t)HD * C];     // [n][k] = Wp[k][n]
__device__ __align__(256) __half g_atthi[(size_t)BATCH * T * HD];
// q,k,v [b][h][t][d] bf16 hi/lo (attention stays 3-split bf16; q pre-scaled D^-1/2)
__device__ __align__(256) __nv_bfloat16 g_qhi[(size_t)BATCH * H * T * D];
__device__ __align__(256) __nv_bfloat16 g_qlo[(size_t)BATCH * H * T * D];
__device__ __align__(256) __nv_bfloat16 g_khi[(size_t)BATCH * H * T * D];
__device__ __align__(256) __nv_bfloat16 g_klo[(size_t)BATCH * H * T * D];
__device__ __align__(256) __nv_bfloat16 g_vhi[(size_t)BATCH * H * T * D];
__device__ __align__(256) __nv_bfloat16 g_vlo[(size_t)BATCH * H * T * D];

// ---------------- helpers (baseline PTX, compute_103-safe) ----------------
__device__ __forceinline__ uint32_t smem_u32(const void* p) {
    uint32_t a;
    asm("{ .reg .u64 t; cvta.to.shared.u64 t, %1; cvt.u32.u64 %0, t; }" : "=r"(a) : "l"(p));
    return a;
}
__device__ __forceinline__ void ldsm4(uint32_t* r, uint32_t addr) {
    asm volatile("ldmatrix.sync.aligned.m8n8.x4.shared.b16 {%0,%1,%2,%3}, [%4];"
        : "=r"(r[0]), "=r"(r[1]), "=r"(r[2]), "=r"(r[3]) : "r"(addr));
}
__device__ __forceinline__ void ldsm4t(uint32_t* r, uint32_t addr) {
    asm volatile("ldmatrix.sync.aligned.m8n8.x4.trans.shared.b16 {%0,%1,%2,%3}, [%4];"
        : "=r"(r[0]), "=r"(r[1]), "=r"(r[2]), "=r"(r[3]) : "r"(addr));
}
// bf16 MMA (attention)
__device__ __forceinline__ void mma16816(float* c, const uint32_t* a, const uint32_t* b) {
    asm volatile("mma.sync.aligned.m16n8k16.row.col.f32.bf16.bf16.f32 "
        "{%0,%1,%2,%3}, {%4,%5,%6,%7}, {%8,%9}, {%0,%1,%2,%3};"
        : "+f"(c[0]), "+f"(c[1]), "+f"(c[2]), "+f"(c[3])
        : "r"(a[0]), "r"(a[1]), "r"(a[2]), "r"(a[3]), "r"(b[0]), "r"(b[1]));
}
// fp16 MMA (projection GEMMs)
__device__ __forceinline__ void mma16816f(float* c, const uint32_t* a, const uint32_t* b) {
    asm volatile("mma.sync.aligned.m16n8k16.row.col.f32.f16.f16.f32 "
        "{%0,%1,%2,%3}, {%4,%5,%6,%7}, {%8,%9}, {%0,%1,%2,%3};"
        : "+f"(c[0]), "+f"(c[1]), "+f"(c[2]), "+f"(c[3])
        : "r"(a[0]), "r"(a[1]), "r"(a[2]), "r"(a[3]), "r"(b[0]), "r"(b[1]));
}
__device__ __forceinline__ void cpa16(uint32_t dst, const void* src) {
    asm volatile("cp.async.cg.shared.global [%0], [%1], 16;" :: "r"(dst), "l"(src));
}
#define CPA_COMMIT() asm volatile("cp.async.commit_group;" ::: "memory")
#define CPA_WAIT1()  asm volatile("cp.async.wait_group 1;" ::: "memory")
#define CPA_WAIT0()  asm volatile("cp.async.wait_group 0;" ::: "memory")

// bf16 hi/lo split helpers (attention inputs)
__device__ __forceinline__ uint32_t cvt_bf16x2(float lo, float hi) {
    uint32_t r;
    asm("cvt.rn.bf16x2.f32 %0, %1, %2;" : "=r"(r) : "f"(hi), "f"(lo));
    return r;
}
__device__ __forceinline__ float lo_f(uint32_t u) { return __uint_as_float(u << 16); }
__device__ __forceinline__ float hi_f(uint32_t u) { return __uint_as_float(u & 0xFFFF0000u); }
__device__ __forceinline__ void hilo_pair(float a, float b, uint32_t& h, uint32_t& l) {
    h = cvt_bf16x2(a, b);
    l = cvt_bf16x2(a - lo_f(h), b - hi_f(h));
}
__device__ __forceinline__ uint32_t pack_f16x2(float a, float b) {
    __half2 h = __floats2half2_rn(a, b);
    return *(uint32_t*)&h;
}

// =================================================================================
// Conversion kernels
// =================================================================================
__global__ void conv_x_kernel(const float* __restrict__ x) {
    size_t i = ((size_t)blockIdx.x * 256 + threadIdx.x) * 4;
    float4 v = *(const float4*)(x + i);
    *(uint32_t*)(g_xhi + i)     = pack_f16x2(v.x, v.y);
    *(uint32_t*)(g_xhi + i + 2) = pack_f16x2(v.z, v.w);
}

__global__ void conv_w_kernel(const float* __restrict__ Wq, const float* __restrict__ Wk,
                              const float* __restrict__ Wv) {
    int idx = blockIdx.x * 256 + threadIdx.x;   // n*C + k
    if (idx >= NQKV * C) return;
    int n = idx / C, k = idx - n * C;
    int which = n / HD, rem = n - which * HD;
    int h = rem >> 6, d = rem & 63;
    const float* W = (which == 0) ? Wq : (which == 1) ? Wk : Wv;
    g_wthi[idx] = __float2half_rn(W[((size_t)h * C + k) * D + d]);
}

__global__ void conv_wp_kernel(const float* __restrict__ Wp) {
    int idx = blockIdx.x * 256 + threadIdx.x;   // n*C + k
    if (idx >= HD * C) return;
    int n = idx / C, k = idx - n * C;
    g_wpthi[idx] = __float2half_rn(Wp[(size_t)k * C + n]);
}

// =================================================================================
// Pure fp16 GEMM: Y[128 x 128] = A[128 x 384] @ B[n][k]^T.
// CTA tile 128x128; 8 warps as 2(m) x 4(n); warp tile 64x32.
// Per k-step/warp: 6 LDSM.x4 + 16 MMAs (192B smem read per MMA).
// Stage (32KB): A@0 (16K), B@16K (16K); double-buffered = 64KB; 2 CTAs/SM.
// =================================================================================
#define STAGE_BYTES 32768
#define GEMM_SMEM (2 * STAGE_BYTES)

template <bool PROJ>
__global__ __launch_bounds__(256, 2)
void mma_gemm(const float* __restrict__ bp, float* __restrict__ out)
{
    extern __shared__ __align__(1024) char sm[];
    const uint32_t smb = smem_u32(sm);
    const int tid = threadIdx.x, wid = tid >> 5, lane = tid & 31;
    const int b = blockIdx.y, n0 = blockIdx.x * 128;
    const int wm = (wid >> 2) * 64;     // 0,64
    const int wn = (wid & 3) * 32;      // 0,32,64,96

    const __half* __restrict__ Ahi = (PROJ ? g_atthi : g_xhi) + (size_t)b * T * C;
    const __half* __restrict__ Bhi = (PROJ ? g_wpthi : g_wthi) + (size_t)n0 * C;

    const int l_row = tid >> 3;          // 0..31
    const int l_seg = tid & 7;

    auto load_chunk = [&](int c, int s) {
        const int c0 = c * 64;
        const uint32_t sb = smb + s * STAGE_BYTES;
#pragma unroll
        for (int p = 0; p < 4; p++) {
            const int row = l_row + p * 32;
            const uint32_t doff = (uint32_t)(row * 128 + ((l_seg ^ (row & 7)) << 4));
            const size_t soff = (size_t)row * C + c0 + l_seg * 8;
            cpa16(sb + doff,         Ahi + soff);
            cpa16(sb + 16384 + doff, Bhi + soff);
        }
        CPA_COMMIT();
    };

    float acc[4][4][4];
#pragma unroll
    for (int i = 0; i < 4; i++)
#pragma unroll
        for (int j = 0; j < 4; j++)
#pragma unroll
            for (int e = 0; e < 4; e++) acc[i][j][e] = 0.f;

    const int rA  = (lane & 7) + ((lane >> 3) & 1) * 8;
    const int khA = lane >> 4;
    const int swA = rA & 7;
    const int rB  = (lane & 7) + (lane >> 4) * 8;
    const int khB = (lane >> 3) & 1;
    const int swB = rB & 7;

    load_chunk(0, 0);
    load_chunk(1, 1);

    for (int c = 0; c < 6; c++) {
        if (c == 5) CPA_WAIT0(); else CPA_WAIT1();
        __syncthreads();

        const uint32_t sb = smb + (c & 1) * STAGE_BYTES;
        const uint32_t aBase = sb + (uint32_t)((wm + rA) * 128);
        const uint32_t bBase = sb + 16384 + (uint32_t)((wn + rB) * 128);

#pragma unroll
        for (int ks = 0; ks < 4; ks++) {
            const uint32_t aoff = (uint32_t)(((ks * 2 + khA) ^ swA) << 4);
            const uint32_t boff = (uint32_t)(((ks * 2 + khB) ^ swB) << 4);
            uint32_t ah[4][4], bh[2][4];
            ldsm4(ah[0], aBase + aoff);
            ldsm4(bh[0], bBase + boff);
            ldsm4(ah[1], aBase + 2048 + aoff);
            ldsm4(bh[1], bBase + 2048 + boff);
            // start MMAs; remaining A LDSMs hide under them
            mma16816f(acc[0][0], ah[0], &bh[0][0]);
            mma16816f(acc[0][1], ah[0], &bh[0][2]);
            ldsm4(ah[2], aBase + 4096 + aoff);
            mma16816f(acc[0][2], ah[0], &bh[1][0]);
            mma16816f(acc[0][3], ah[0], &bh[1][2]);
            ldsm4(ah[3], aBase + 6144 + aoff);
            mma16816f(acc[1][0], ah[1], &bh[0][0]);
            mma16816f(acc[1][1], ah[1], &bh[0][2]);
            mma16816f(acc[1][2], ah[1], &bh[1][0]);
            mma16816f(acc[1][3], ah[1], &bh[1][2]);
#pragma unroll
            for (int mf = 2; mf < 4; mf++) {
                mma16816f(acc[mf][0], ah[mf], &bh[0][0]);
                mma16816f(acc[mf][1], ah[mf], &bh[0][2]);
                mma16816f(acc[mf][2], ah[mf], &bh[1][0]);
                mma16816f(acc[mf][3], ah[mf], &bh[1][2]);
            }
        }
        __syncthreads();
        if (c + 2 < 6) load_chunk(c + 2, (c & 1));
    }

    // ---------------- epilogue ----------------
    const int qrow = lane >> 2;
    const int qcol = (lane & 3) * 2;

    if (PROJ) {
#pragma unroll
        for (int mf = 0; mf < 4; mf++) {
#pragma unroll
            for (int nf = 0; nf < 4; nf++) {
                const int row = wm + mf * 16 + qrow;
                const int col = n0 + wn + nf * 8 + qcol;
                const float2 bb = *(const float2*)(bp + col);
                float* p0 = out + ((size_t)b * T + row) * HD + col;
                float* p1 = out + ((size_t)b * T + row + 8) * HD + col;
                *(float2*)p0 = make_float2(acc[mf][nf][0] + bb.x, acc[mf][nf][1] + bb.y);
                *(float2*)p1 = make_float2(acc[mf][nf][2] + bb.x, acc[mf][nf][3] + bb.y);
            }
        }
    } else {
        const int which = blockIdx.x / 3;       // 0=q,1=k,2=v (3 tiles of 128 per which)
        const int rem0 = (blockIdx.x % 3) * 128;
        __nv_bfloat16* bh_ = (which == 0) ? g_qhi : (which == 1) ? g_khi : g_vhi;
        __nv_bfloat16* bl_ = (which == 0) ? g_qlo : (which == 1) ? g_klo : g_vlo;
        const float scale = (which == 0) ? 0.125f : 1.0f;   // q pre-scaled by D^-1/2
#pragma unroll
        for (int mf = 0; mf < 4; mf++) {
#pragma unroll
            for (int nf = 0; nf < 4; nf++) {
                const int row = wm + mf * 16 + qrow;
                const int rem = rem0 + wn + nf * 8 + qcol;
                const int hh = rem >> 6, dd = rem & 63;
                const size_t o0 = (((size_t)(b * H + hh) * T) + row) * D + dd;
                uint32_t hi, lo;
                hilo_pair(acc[mf][nf][0] * scale, acc[mf][nf][1] * scale, hi, lo);
                *(uint32_t*)(bh_ + o0) = hi;
                *(uint32_t*)(bl_ + o0) = lo;
                hilo_pair(acc[mf][nf][2] * scale, acc[mf][nf][3] * scale, hi, lo);
                *(uint32_t*)(bh_ + o0 + 8 * D) = hi;
                *(uint32_t*)(bl_ + o0 + 8 * D) = lo;
            }
        }
    }
}

// =================================================================================
// MMA attention per (b, h) — bf16 3-split (unchanged math), emits att fp16.
// =================================================================================
#define ATTN_SMEM 98304

__global__ __launch_bounds__(256, 1)
void attn_mma()
{
    extern __shared__ __align__(1024) char sm[];
    const uint32_t smb = smem_u32(sm);
    const int tid = threadIdx.x, w = tid >> 5, lane = tid & 31;
    const int b = blockIdx.x, h = blockIdx.y;
    const int rb = (w < 4) ? w : (11 - w);     // row-block; SMSP pairs balanced

    const size_t blk = (size_t)(b * H + h) * (T * D);
    {
        const int seg = tid & 7;
#pragma unroll
        for (int p = 0; p < 4; p++) {
            const int row = (tid + p * 256) >> 3;          // 0..127
            const uint32_t doff = (uint32_t)(row * 128 + ((seg ^ (row & 7)) << 4));
            const size_t soff = blk + (size_t)row * D + seg * 8;
            cpa16(smb + doff,         g_qhi + soff);
            cpa16(smb + 16384 + doff, g_qlo + soff);
            cpa16(smb + 32768 + doff, g_khi + soff);
            cpa16(smb + 49152 + doff, g_klo + soff);
            cpa16(smb + 65536 + doff, g_vhi + soff);
            cpa16(smb + 81920 + doff, g_vlo + soff);
        }
    }
    CPA_COMMIT();
    CPA_WAIT0();
    __syncthreads();

    const int rA  = (lane & 7) + ((lane >> 3) & 1) * 8;
    const int khA = lane >> 4;
    const int swA = rA & 7;
    const int rB  = (lane & 7) + (lane >> 4) * 8;
    const int khB = (lane >> 3) & 1;
    const int swB = rB & 7;

    const uint32_t aQhi = smb + (uint32_t)((rb * 16 + rA) * 128);
    const uint32_t aQlo = aQhi + 16384;

    // ---------------- S = Q @ K^T (3-split, causal block-skip) ----------------
    float S[16][4];
#pragma unroll
    for (int i = 0; i < 16; i++)
#pragma unroll
        for (int e = 0; e < 4; e++) S[i][e] = 0.f;

#pragma unroll
    for (int ks = 0; ks < 4; ks++) {
        uint32_t qh[4], ql[4];
        const uint32_t aoff = (uint32_t)(((ks * 2 + khA) ^ swA) << 4);
        ldsm4(qh, aQhi + aoff);
        ldsm4(ql, aQlo + aoff);
        const uint32_t boff = (uint32_t)(((ks * 2 + khB) ^ swB) << 4);
#pragma unroll
        for (int g = 0; g < 8; g += 2) {
            if (g > rb) break;
            uint32_t kh0[4], kl0[4];
            const uint32_t bb0 = smb + 32768 + (uint32_t)((g * 16 + rB) * 128);
            ldsm4(kh0, bb0 + boff);
            mma16816(S[2 * g],     qh, &kh0[0]);
            ldsm4(kl0, bb0 + 16384 + boff);
            mma16816(S[2 * g + 1], qh, &kh0[2]);
            const bool g1ok = (g + 1) <= rb;
            uint32_t kh1[4], kl1[4];
            if (g1ok) {
                const uint32_t bb1 = smb + 32768 + (uint32_t)(((g + 1) * 16 + rB) * 128);
                ldsm4(kh1, bb1 + boff);
                ldsm4(kl1, bb1 + 16384 + boff);
            }
            mma16816(S[2 * g],     qh, &kl0[0]);
            mma16816(S[2 * g + 1], qh, &kl0[2]);
            mma16816(S[2 * g],     ql, &kh0[0]);
            mma16816(S[2 * g + 1], ql, &kh0[2]);
            if (g1ok) {
                mma16816(S[2 * g + 2], qh, &kh1[0]);
                mma16816(S[2 * g + 3], qh, &kh1[2]);
                mma16816(S[2 * g + 2], qh, &kl1[0]);
                mma16816(S[2 * g + 3], qh, &kl1[2]);
                mma16816(S[2 * g + 2], ql, &kh1[0]);
                mma16816(S[2 * g + 3], ql, &kh1[2]);
            }
        }
    }

    // ---------------- softmax exponentials (q already scaled by D^-1/2) ----------
    const int row0 = rb * 16 + (lane >> 2);
    const int row1 = row0 + 8;
    const int colb = 2 * (lane & 3);
    float sum0 = 0.f, sum1 = 0.f;
#pragma unroll
    for (int nf = 0; nf < 16; nf++) {
        if (nf > 2 * rb + 1) break;
        const int c0 = nf * 8 + colb, c1 = c0 + 1;
        float e00 = (c0 <= row0) ? __expf(S[nf][0]) : 0.f;
        float e01 = (c1 <= row0) ? __expf(S[nf][1]) : 0.f;
        float e10 = (c0 <= row1) ? __expf(S[nf][2]) : 0.f;
        float e11 = (c1 <= row1) ? __expf(S[nf][3]) : 0.f;
        S[nf][0] = e00; S[nf][1] = e01; S[nf][2] = e10; S[nf][3] = e11;
        sum0 += e00 + e01;
        sum1 += e10 + e11;
    }
    sum0 += __shfl_xor_sync(0xFFFFFFFFu, sum0, 1);
    sum0 += __shfl_xor_sync(0xFFFFFFFFu, sum0, 2);
    sum1 += __shfl_xor_sync(0xFFFFFFFFu, sum1, 1);
    sum1 += __shfl_xor_sync(0xFFFFFFFFu, sum1, 2);
    const float inv0 = 1.0f / sum0;
    const float inv1 = 1.0f / sum1;

    // ---------------- O = (raw P) @ V; normalization applied in epilogue --------
    float O[8][4];
#pragma unroll
    for (int i = 0; i < 8; i++)
#pragma unroll
        for (int e = 0; e < 4; e++) O[i][e] = 0.f;

    const int mT = lane >> 3;
    const int rT = lane & 7;

#pragma unroll
    for (int ks = 0; ks < 8; ks++) {
        if (ks > rb) break;
        const int srow = ks * 16 + (mT & 1) * 8 + rT;
        const uint32_t rowOff = (uint32_t)(srow * 128);
        uint32_t vh[4][4], vl[4][4];
        {
            const int dseg0 = (mT >> 1);
            const uint32_t a0 = rowOff + (uint32_t)(((dseg0 ^ (srow & 7)) << 4));
            ldsm4t(vh[0], smb + 65536 + a0);
            ldsm4t(vl[0], smb + 81920 + a0);
        }
        uint32_t phi[4], plo[4];
        hilo_pair(S[2 * ks][0],     S[2 * ks][1],     phi[0], plo[0]);
        hilo_pair(S[2 * ks][2],     S[2 * ks][3],     phi[1], plo[1]);
        hilo_pair(S[2 * ks + 1][0], S[2 * ks + 1][1], phi[2], plo[2]);
        hilo_pair(S[2 * ks + 1][2], S[2 * ks + 1][3], phi[3], plo[3]);
#pragma unroll
        for (int g = 1; g < 4; g++) {
            const int dseg = g * 2 + (mT >> 1);
            const uint32_t addr = rowOff + (uint32_t)(((dseg ^ (srow & 7)) << 4));
            ldsm4t(vh[g], smb + 65536 + addr);
            mma16816(O[2 * (g - 1)],     phi, &vh[g - 1][0]);
            mma16816(O[2 * (g - 1) + 1], phi, &vh[g - 1][2]);
            ldsm4t(vl[g], smb + 81920 + addr);
            mma16816(O[2 * (g - 1)],     phi, &vl[g - 1][0]);
            mma16816(O[2 * (g - 1) + 1], phi, &vl[g - 1][2]);
        }
        mma16816(O[6], phi, &vh[3][0]);
        mma16816(O[7], phi, &vh[3][2]);
        mma16816(O[6], phi, &vl[3][0]);
        mma16816(O[7], phi, &vl[3][2]);
#pragma unroll
        for (int g = 0; g < 4; g++) {
            mma16816(O[2 * g],     plo, &vh[g][0]);
            mma16816(O[2 * g + 1], plo, &vh[g][2]);
        }
    }

    // ---------------- epilogue: normalize, att fp16 [b][t][h*64+d] ---------
    const size_t obase = (size_t)b * T * HD + h * D;
#pragma unroll
    for (int nf = 0; nf < 8; nf++) {
        const int d0 = nf * 8 + colb;
        *(uint32_t*)(g_atthi + obase + (size_t)row0 * HD + d0) =
            pack_f16x2(O[nf][0] * inv0, O[nf][1] * inv0);
        *(uint32_t*)(g_atthi + obase + (size_t)row1 * HD + d0) =
            pack_f16x2(O[nf][2] * inv1, O[nf][3] * inv1);
    }
}

// =================================================================================
extern "C" void kernel_launch(void* const* d_in, const int* in_sizes, int n_in,
                              void* d_out, int out_size)
{
    (void)in_sizes; (void)n_in; (void)out_size;
    const float* x  = (const float*)d_in[0];
    const float* Wq = (const float*)d_in[1];
    const float* Wk = (const float*)d_in[2];
    const float* Wv = (const float*)d_in[3];
    const float* Wp = (const float*)d_in[4];
    const float* bp = (const float*)d_in[5];
    float* out = (float*)d_out;

    cudaFuncSetAttribute(mma_gemm<false>, cudaFuncAttributeMaxDynamicSharedMemorySize, GEMM_SMEM);
    cudaFuncSetAttribute(mma_gemm<true>,  cudaFuncAttributeMaxDynamicSharedMemorySize, GEMM_SMEM);
    cudaFuncSetAttribute(attn_mma, cudaFuncAttributeMaxDynamicSharedMemorySize, ATTN_SMEM);

    conv_x_kernel<<<(BATCH * T * C / 4) / 256, 256>>>(x);
    conv_w_kernel<<<(NQKV * C + 255) / 256, 256>>>(Wq, Wk, Wv);
    conv_wp_kernel<<<(HD * C + 255) / 256, 256>>>(Wp);

    mma_gemm<false><<<dim3(9, BATCH), 256, GEMM_SMEM>>>(nullptr, nullptr);
    attn_mma<<<dim3(BATCH, H), 256, ATTN_SMEM>>>();
    mma_gemm<true><<<dim3(3, BATCH), 256, GEMM_SMEM>>>(bp, out);
}

// round 11
// speedup vs baseline: 2.0452x; 1.1413x over previous
#include <cuda_runtime.h>
#include <cuda_fp16.h>
#include <cstdint>

#define BATCH 512
#define T 128
#define C 384
#define H 6
#define D 64
#define HD 384
#define NQKV 1152

// ---------------- scratch (device globals; no runtime allocation) ----------------
__device__ __align__(256) __half g_xhi[(size_t)BATCH * T * C];
__device__ __align__(256) __half g_wthi[(size_t)NQKV * C];    // [n][k]
__device__ __align__(256) __half g_wpthi[(size_t)HD * C];     // [n][k] = Wp[k][n]
__device__ __align__(256) __half g_atthi[(size_t)BATCH * T * HD];
// q fp16 hi/lo (pre-scaled D^-1/2); k, v single fp16; all [b][h][t][d]
__device__ __align__(256) __half g_qh[(size_t)BATCH * H * T * D];
__device__ __align__(256) __half g_ql[(size_t)BATCH * H * T * D];
__device__ __align__(256) __half g_k [(size_t)BATCH * H * T * D];
__device__ __align__(256) __half g_v [(size_t)BATCH * H * T * D];

// ---------------- helpers (baseline PTX, compute_103-safe) ----------------
__device__ __forceinline__ uint32_t smem_u32(const void* p) {
    uint32_t a;
    asm("{ .reg .u64 t; cvta.to.shared.u64 t, %1; cvt.u32.u64 %0, t; }" : "=r"(a) : "l"(p));
    return a;
}
__device__ __forceinline__ void ldsm4(uint32_t* r, uint32_t addr) {
    asm volatile("ldmatrix.sync.aligned.m8n8.x4.shared.b16 {%0,%1,%2,%3}, [%4];"
        : "=r"(r[0]), "=r"(r[1]), "=r"(r[2]), "=r"(r[3]) : "r"(addr));
}
__device__ __forceinline__ void ldsm4t(uint32_t* r, uint32_t addr) {
    asm volatile("ldmatrix.sync.aligned.m8n8.x4.trans.shared.b16 {%0,%1,%2,%3}, [%4];"
        : "=r"(r[0]), "=r"(r[1]), "=r"(r[2]), "=r"(r[3]) : "r"(addr));
}
// fp16 MMA, fp32 accum
__device__ __forceinline__ void mma16816f(float* c, const uint32_t* a, const uint32_t* b) {
    asm volatile("mma.sync.aligned.m16n8k16.row.col.f32.f16.f16.f32 "
        "{%0,%1,%2,%3}, {%4,%5,%6,%7}, {%8,%9}, {%0,%1,%2,%3};"
        : "+f"(c[0]), "+f"(c[1]), "+f"(c[2]), "+f"(c[3])
        : "r"(a[0]), "r"(a[1]), "r"(a[2]), "r"(a[3]), "r"(b[0]), "r"(b[1]));
}
__device__ __forceinline__ void cpa16(uint32_t dst, const void* src) {
    asm volatile("cp.async.cg.shared.global [%0], [%1], 16;" :: "r"(dst), "l"(src));
}
#define CPA_COMMIT() asm volatile("cp.async.commit_group;" ::: "memory")
#define CPA_WAIT1()  asm volatile("cp.async.wait_group 1;" ::: "memory")
#define CPA_WAIT0()  asm volatile("cp.async.wait_group 0;" ::: "memory")

__device__ __forceinline__ uint32_t pack_f16x2(float a, float b) {
    __half2 h = __floats2half2_rn(a, b);
    return *(uint32_t*)&h;
}
// fp16 hi/lo split
__device__ __forceinline__ void hilo_pair_f16(float a, float b, uint32_t& h, uint32_t& l) {
    __half ha = __float2half_rn(a), hb = __float2half_rn(b);
    __half la = __float2half_rn(a - __half2float(ha));
    __half lb = __float2half_rn(b - __half2float(hb));
    h = (uint32_t)__half_as_ushort(ha) | ((uint32_t)__half_as_ushort(hb) << 16);
    l = (uint32_t)__half_as_ushort(la) | ((uint32_t)__half_as_ushort(lb) << 16);
}

// =================================================================================
// Conversion kernels
// =================================================================================
__global__ void conv_x_kernel(const float* __restrict__ x) {
    size_t i = ((size_t)blockIdx.x * 256 + threadIdx.x) * 4;
    float4 v = *(const float4*)(x + i);
    *(uint32_t*)(g_xhi + i)     = pack_f16x2(v.x, v.y);
    *(uint32_t*)(g_xhi + i + 2) = pack_f16x2(v.z, v.w);
}

__global__ void conv_w_kernel(const float* __restrict__ Wq, const float* __restrict__ Wk,
                              const float* __restrict__ Wv) {
    int idx = blockIdx.x * 256 + threadIdx.x;   // n*C + k
    if (idx >= NQKV * C) return;
    int n = idx / C, k = idx - n * C;
    int which = n / HD, rem = n - which * HD;
    int h = rem >> 6, d = rem & 63;
    const float* W = (which == 0) ? Wq : (which == 1) ? Wk : Wv;
    g_wthi[idx] = __float2half_rn(W[((size_t)h * C + k) * D + d]);
}

__global__ void conv_wp_kernel(const float* __restrict__ Wp) {
    int idx = blockIdx.x * 256 + threadIdx.x;   // n*C + k
    if (idx >= HD * C) return;
    int n = idx / C, k = idx - n * C;
    g_wpthi[idx] = __float2half_rn(Wp[(size_t)k * C + n]);
}

// =================================================================================
// Pure fp16 GEMM: Y[128 x 128] = A[128 x 384] @ B[n][k]^T.  (at HMMA-f32acc ceiling)
// =================================================================================
#define STAGE_BYTES 32768
#define GEMM_SMEM (2 * STAGE_BYTES)

template <bool PROJ>
__global__ __launch_bounds__(256, 2)
void mma_gemm(const float* __restrict__ bp, float* __restrict__ out)
{
    extern __shared__ __align__(1024) char sm[];
    const uint32_t smb = smem_u32(sm);
    const int tid = threadIdx.x, wid = tid >> 5, lane = tid & 31;
    const int b = blockIdx.y, n0 = blockIdx.x * 128;
    const int wm = (wid >> 2) * 64;     // 0,64
    const int wn = (wid & 3) * 32;      // 0,32,64,96

    const __half* __restrict__ Ahi = (PROJ ? g_atthi : g_xhi) + (size_t)b * T * C;
    const __half* __restrict__ Bhi = (PROJ ? g_wpthi : g_wthi) + (size_t)n0 * C;

    const int l_row = tid >> 3;          // 0..31
    const int l_seg = tid & 7;

    auto load_chunk = [&](int c, int s) {
        const int c0 = c * 64;
        const uint32_t sb = smb + s * STAGE_BYTES;
#pragma unroll
        for (int p = 0; p < 4; p++) {
            const int row = l_row + p * 32;
            const uint32_t doff = (uint32_t)(row * 128 + ((l_seg ^ (row & 7)) << 4));
            const size_t soff = (size_t)row * C + c0 + l_seg * 8;
            cpa16(sb + doff,         Ahi + soff);
            cpa16(sb + 16384 + doff, Bhi + soff);
        }
        CPA_COMMIT();
    };

    float acc[4][4][4];
#pragma unroll
    for (int i = 0; i < 4; i++)
#pragma unroll
        for (int j = 0; j < 4; j++)
#pragma unroll
            for (int e = 0; e < 4; e++) acc[i][j][e] = 0.f;

    const int rA  = (lane & 7) + ((lane >> 3) & 1) * 8;
    const int khA = lane >> 4;
    const int swA = rA & 7;
    const int rB  = (lane & 7) + (lane >> 4) * 8;
    const int khB = (lane >> 3) & 1;
    const int swB = rB & 7;

    load_chunk(0, 0);
    load_chunk(1, 1);

    for (int c = 0; c < 6; c++) {
        if (c == 5) CPA_WAIT0(); else CPA_WAIT1();
        __syncthreads();

        const uint32_t sb = smb + (c & 1) * STAGE_BYTES;
        const uint32_t aBase = sb + (uint32_t)((wm + rA) * 128);
        const uint32_t bBase = sb + 16384 + (uint32_t)((wn + rB) * 128);

#pragma unroll
        for (int ks = 0; ks < 4; ks++) {
            const uint32_t aoff = (uint32_t)(((ks * 2 + khA) ^ swA) << 4);
            const uint32_t boff = (uint32_t)(((ks * 2 + khB) ^ swB) << 4);
            uint32_t ah[4][4], bh[2][4];
            ldsm4(ah[0], aBase + aoff);
            ldsm4(bh[0], bBase + boff);
            ldsm4(ah[1], aBase + 2048 + aoff);
            ldsm4(bh[1], bBase + 2048 + boff);
            mma16816f(acc[0][0], ah[0], &bh[0][0]);
            mma16816f(acc[0][1], ah[0], &bh[0][2]);
            ldsm4(ah[2], aBase + 4096 + aoff);
            mma16816f(acc[0][2], ah[0], &bh[1][0]);
            mma16816f(acc[0][3], ah[0], &bh[1][2]);
            ldsm4(ah[3], aBase + 6144 + aoff);
            mma16816f(acc[1][0], ah[1], &bh[0][0]);
            mma16816f(acc[1][1], ah[1], &bh[0][2]);
            mma16816f(acc[1][2], ah[1], &bh[1][0]);
            mma16816f(acc[1][3], ah[1], &bh[1][2]);
#pragma unroll
            for (int mf = 2; mf < 4; mf++) {
                mma16816f(acc[mf][0], ah[mf], &bh[0][0]);
                mma16816f(acc[mf][1], ah[mf], &bh[0][2]);
                mma16816f(acc[mf][2], ah[mf], &bh[1][0]);
                mma16816f(acc[mf][3], ah[mf], &bh[1][2]);
            }
        }
        __syncthreads();
        if (c + 2 < 6) load_chunk(c + 2, (c & 1));
    }

    // ---------------- epilogue ----------------
    const int qrow = lane >> 2;
    const int qcol = (lane & 3) * 2;

    if (PROJ) {
#pragma unroll
        for (int mf = 0; mf < 4; mf++) {
#pragma unroll
            for (int nf = 0; nf < 4; nf++) {
                const int row = wm + mf * 16 + qrow;
                const int col = n0 + wn + nf * 8 + qcol;
                const float2 bb = *(const float2*)(bp + col);
                float* p0 = out + ((size_t)b * T + row) * HD + col;
                float* p1 = out + ((size_t)b * T + row + 8) * HD + col;
                *(float2*)p0 = make_float2(acc[mf][nf][0] + bb.x, acc[mf][nf][1] + bb.y);
                *(float2*)p1 = make_float2(acc[mf][nf][2] + bb.x, acc[mf][nf][3] + bb.y);
            }
        }
    } else {
        const int which = blockIdx.x / 3;       // 0=q,1=k,2=v (3 tiles of 128 per which)
        const int rem0 = (blockIdx.x % 3) * 128;
#pragma unroll
        for (int mf = 0; mf < 4; mf++) {
#pragma unroll
            for (int nf = 0; nf < 4; nf++) {
                const int row = wm + mf * 16 + qrow;
                const int rem = rem0 + wn + nf * 8 + qcol;
                const int hh = rem >> 6, dd = rem & 63;
                const size_t o0 = (((size_t)(b * H + hh) * T) + row) * D + dd;
                if (which == 0) {
                    // q: pre-scale by D^-1/2, fp16 hi/lo
                    uint32_t hi, lo;
                    hilo_pair_f16(acc[mf][nf][0] * 0.125f, acc[mf][nf][1] * 0.125f, hi, lo);
                    *(uint32_t*)(g_qh + o0) = hi;
                    *(uint32_t*)(g_ql + o0) = lo;
                    hilo_pair_f16(acc[mf][nf][2] * 0.125f, acc[mf][nf][3] * 0.125f, hi, lo);
                    *(uint32_t*)(g_qh + o0 + 8 * D) = hi;
                    *(uint32_t*)(g_ql + o0 + 8 * D) = lo;
                } else {
                    __half* dst = (which == 1) ? g_k : g_v;
                    *(uint32_t*)(dst + o0) = pack_f16x2(acc[mf][nf][0], acc[mf][nf][1]);
                    *(uint32_t*)(dst + o0 + 8 * D) = pack_f16x2(acc[mf][nf][2], acc[mf][nf][3]);
                }
            }
        }
    }
}

// =================================================================================
// MMA attention per (b, h): Q fp16 2-term, K/V single fp16, P fp16 2-term (regs).
// smem: qh@0 (16K), ql@16K, k@32K, v@48K  => 64KB.
// =================================================================================
#define ATTN_SMEM 65536

__global__ __launch_bounds__(256, 1)
void attn_mma()
{
    extern __shared__ __align__(1024) char sm[];
    const uint32_t smb = smem_u32(sm);
    const int tid = threadIdx.x, w = tid >> 5, lane = tid & 31;
    const int b = blockIdx.x, h = blockIdx.y;
    const int rb = (w < 4) ? w : (11 - w);     // row-block; SMSP pairs balanced

    const size_t blk = (size_t)(b * H + h) * (T * D);
    {
        const int seg = tid & 7;
#pragma unroll
        for (int p = 0; p < 4; p++) {
            const int row = (tid + p * 256) >> 3;          // 0..127
            const uint32_t doff = (uint32_t)(row * 128 + ((seg ^ (row & 7)) << 4));
            const size_t soff = blk + (size_t)row * D + seg * 8;
            cpa16(smb + doff,         g_qh + soff);
            cpa16(smb + 16384 + doff, g_ql + soff);
            cpa16(smb + 32768 + doff, g_k  + soff);
            cpa16(smb + 49152 + doff, g_v  + soff);
        }
    }
    CPA_COMMIT();
    CPA_WAIT0();
    __syncthreads();

    const int rA  = (lane & 7) + ((lane >> 3) & 1) * 8;
    const int khA = lane >> 4;
    const int swA = rA & 7;
    const int rB  = (lane & 7) + (lane >> 4) * 8;
    const int khB = (lane >> 3) & 1;
    const int swB = rB & 7;

    const uint32_t aQh = smb + (uint32_t)((rb * 16 + rA) * 128);
    const uint32_t aQl = aQh + 16384;

    // ---------------- S = Q @ K^T (2-term, causal block-skip) ----------------
    float S[16][4];
#pragma unroll
    for (int i = 0; i < 16; i++)
#pragma unroll
        for (int e = 0; e < 4; e++) S[i][e] = 0.f;

#pragma unroll
    for (int ks = 0; ks < 4; ks++) {
        uint32_t qh[4], ql[4];
        const uint32_t aoff = (uint32_t)(((ks * 2 + khA) ^ swA) << 4);
        ldsm4(qh, aQh + aoff);
        ldsm4(ql, aQl + aoff);
        const uint32_t boff = (uint32_t)(((ks * 2 + khB) ^ swB) << 4);
#pragma unroll
        for (int g = 0; g < 8; g += 2) {
            if (g > rb) break;
            uint32_t kh0[4];
            const uint32_t bb0 = smb + 32768 + (uint32_t)((g * 16 + rB) * 128);
            ldsm4(kh0, bb0 + boff);
            const bool g1ok = (g + 1) <= rb;
            uint32_t kh1[4];
            if (g1ok) {
                const uint32_t bb1 = smb + 32768 + (uint32_t)(((g + 1) * 16 + rB) * 128);
                ldsm4(kh1, bb1 + boff);
            }
            mma16816f(S[2 * g],     qh, &kh0[0]);
            mma16816f(S[2 * g + 1], qh, &kh0[2]);
            mma16816f(S[2 * g],     ql, &kh0[0]);
            mma16816f(S[2 * g + 1], ql, &kh0[2]);
            if (g1ok) {
                mma16816f(S[2 * g + 2], qh, &kh1[0]);
                mma16816f(S[2 * g + 3], qh, &kh1[2]);
                mma16816f(S[2 * g + 2], ql, &kh1[0]);
                mma16816f(S[2 * g + 3], ql, &kh1[2]);
            }
        }
    }

    // ---------------- softmax exponentials (q pre-scaled by D^-1/2) ----------
    const int row0 = rb * 16 + (lane >> 2);
    const int row1 = row0 + 8;
    const int colb = 2 * (lane & 3);
    float sum0 = 0.f, sum1 = 0.f;
#pragma unroll
    for (int nf = 0; nf < 16; nf++) {
        if (nf > 2 * rb + 1) break;
        const int c0 = nf * 8 + colb, c1 = c0 + 1;
        float e00 = (c0 <= row0) ? __expf(S[nf][0]) : 0.f;
        float e01 = (c1 <= row0) ? __expf(S[nf][1]) : 0.f;
        float e10 = (c0 <= row1) ? __expf(S[nf][2]) : 0.f;
        float e11 = (c1 <= row1) ? __expf(S[nf][3]) : 0.f;
        S[nf][0] = e00; S[nf][1] = e01; S[nf][2] = e10; S[nf][3] = e11;
        sum0 += e00 + e01;
        sum1 += e10 + e11;
    }
    sum0 += __shfl_xor_sync(0xFFFFFFFFu, sum0, 1);
    sum0 += __shfl_xor_sync(0xFFFFFFFFu, sum0, 2);
    sum1 += __shfl_xor_sync(0xFFFFFFFFu, sum1, 1);
    sum1 += __shfl_xor_sync(0xFFFFFFFFu, sum1, 2);
    const float inv0 = 1.0f / sum0;
    const float inv1 = 1.0f / sum1;

    // ---------------- O = (raw P) @ V; P fp16 hi/lo, V single fp16 --------
    float O[8][4];
#pragma unroll
    for (int i = 0; i < 8; i++)
#pragma unroll
        for (int e = 0; e < 4; e++) O[i][e] = 0.f;

    const int mT = lane >> 3;
    const int rT = lane & 7;

#pragma unroll
    for (int ks = 0; ks < 8; ks++) {
        if (ks > rb) break;
        const int srow = ks * 16 + (mT & 1) * 8 + rT;
        const uint32_t rowOff = (uint32_t)(srow * 128);
        uint32_t vh[4][4];
        {
            const int dseg0 = (mT >> 1);
            const uint32_t a0 = rowOff + (uint32_t)(((dseg0 ^ (srow & 7)) << 4));
            ldsm4t(vh[0], smb + 49152 + a0);
        }
        uint32_t phi[4], plo[4];
        hilo_pair_f16(S[2 * ks][0],     S[2 * ks][1],     phi[0], plo[0]);
        hilo_pair_f16(S[2 * ks][2],     S[2 * ks][3],     phi[1], plo[1]);
        hilo_pair_f16(S[2 * ks + 1][0], S[2 * ks + 1][1], phi[2], plo[2]);
        hilo_pair_f16(S[2 * ks + 1][2], S[2 * ks + 1][3], phi[3], plo[3]);
#pragma unroll
        for (int g = 1; g < 4; g++) {
            const int dseg = g * 2 + (mT >> 1);
            const uint32_t addr = rowOff + (uint32_t)(((dseg ^ (srow & 7)) << 4));
            ldsm4t(vh[g], smb + 49152 + addr);
            mma16816f(O[2 * (g - 1)],     phi, &vh[g - 1][0]);
            mma16816f(O[2 * (g - 1) + 1], phi, &vh[g - 1][2]);
            mma16816f(O[2 * (g - 1)],     plo, &vh[g - 1][0]);
            mma16816f(O[2 * (g - 1) + 1], plo, &vh[g - 1][2]);
        }
        mma16816f(O[6], phi, &vh[3][0]);
        mma16816f(O[7], phi, &vh[3][2]);
        mma16816f(O[6], plo, &vh[3][0]);
        mma16816f(O[7], plo, &vh[3][2]);
    }

    // ---------------- epilogue: normalize, att fp16 [b][t][h*64+d] ---------
    const size_t obase = (size_t)b * T * HD + h * D;
#pragma unroll
    for (int nf = 0; nf < 8; nf++) {
        const int d0 = nf * 8 + colb;
        *(uint32_t*)(g_atthi + obase + (size_t)row0 * HD + d0) =
            pack_f16x2(O[nf][0] * inv0, O[nf][1] * inv0);
        *(uint32_t*)(g_atthi + obase + (size_t)row1 * HD + d0) =
            pack_f16x2(O[nf][2] * inv1, O[nf][3] * inv1);
    }
}

// =================================================================================
extern "C" void kernel_launch(void* const* d_in, const int* in_sizes, int n_in,
                              void* d_out, int out_size)
{
    (void)in_sizes; (void)n_in; (void)out_size;
    const float* x  = (const float*)d_in[0];
    const float* Wq = (const float*)d_in[1];
    const float* Wk = (const float*)d_in[2];
    const float* Wv = (const float*)d_in[3];
    const float* Wp = (const float*)d_in[4];
    const float* bp = (const float*)d_in[5];
    float* out = (float*)d_out;

    cudaFuncSetAttribute(mma_gemm<false>, cudaFuncAttributeMaxDynamicSharedMemorySize, GEMM_SMEM);
    cudaFuncSetAttribute(mma_gemm<true>,  cudaFuncAttributeMaxDynamicSharedMemorySize, GEMM_SMEM);
    cudaFuncSetAttribute(attn_mma, cudaFuncAttributeMaxDynamicSharedMemorySize, ATTN_SMEM);

    conv_x_kernel<<<(BATCH * T * C / 4) / 256, 256>>>(x);
    conv_w_kernel<<<(NQKV * C + 255) / 256, 256>>>(Wq, Wk, Wv);
    conv_wp_kernel<<<(HD * C + 255) / 256, 256>>>(Wp);

    mma_gemm<false><<<dim3(9, BATCH), 256, GEMM_SMEM>>>(nullptr, nullptr);
    attn_mma<<<dim3(BATCH, H), 256, ATTN_SMEM>>>();
    mma_gemm<true><<<dim3(3, BATCH), 256, GEMM_SMEM>>>(bp, out);
}

// round 12
// speedup vs baseline: 2.3664x; 1.1571x over previous
#include <cuda_runtime.h>
#include <cuda_fp16.h>
#include <cstdint>

#define BATCH 512
#define T 128
#define C 384
#define H 6
#define D 64
#define HD 384
#define NQKV 1152

// ---------------- scratch (device globals; no runtime allocation) ----------------
__device__ __align__(256) __half g_xhi[(size_t)BATCH * T * C];
__device__ __align__(256) __half g_wthi[(size_t)NQKV * C];    // [n][k]
__device__ __align__(256) __half g_wpthi[(size_t)HD * C];     // [n][k] = Wp[k][n]
__device__ __align__(256) __half g_atthi[(size_t)BATCH * T * HD];
// q (pre-scaled D^-1/2), k, v single fp16; all [b][h][t][d]
__device__ __align__(256) __half g_q[(size_t)BATCH * H * T * D];
__device__ __align__(256) __half g_k[(size_t)BATCH * H * T * D];
__device__ __align__(256) __half g_v[(size_t)BATCH * H * T * D];

// ---------------- helpers (baseline PTX, compute_103-safe) ----------------
__device__ __forceinline__ uint32_t smem_u32(const void* p) {
    uint32_t a;
    asm("{ .reg .u64 t; cvta.to.shared.u64 t, %1; cvt.u32.u64 %0, t; }" : "=r"(a) : "l"(p));
    return a;
}
__device__ __forceinline__ void ldsm4(uint32_t* r, uint32_t addr) {
    asm volatile("ldmatrix.sync.aligned.m8n8.x4.shared.b16 {%0,%1,%2,%3}, [%4];"
        : "=r"(r[0]), "=r"(r[1]), "=r"(r[2]), "=r"(r[3]) : "r"(addr));
}
__device__ __forceinline__ void ldsm4t(uint32_t* r, uint32_t addr) {
    asm volatile("ldmatrix.sync.aligned.m8n8.x4.trans.shared.b16 {%0,%1,%2,%3}, [%4];"
        : "=r"(r[0]), "=r"(r[1]), "=r"(r[2]), "=r"(r[3]) : "r"(addr));
}
// fp16 MMA, fp32 accum
__device__ __forceinline__ void mma16816f(float* c, const uint32_t* a, const uint32_t* b) {
    asm volatile("mma.sync.aligned.m16n8k16.row.col.f32.f16.f16.f32 "
        "{%0,%1,%2,%3}, {%4,%5,%6,%7}, {%8,%9}, {%0,%1,%2,%3};"
        : "+f"(c[0]), "+f"(c[1]), "+f"(c[2]), "+f"(c[3])
        : "r"(a[0]), "r"(a[1]), "r"(a[2]), "r"(a[3]), "r"(b[0]), "r"(b[1]));
}
__device__ __forceinline__ void cpa16(uint32_t dst, const void* src) {
    asm volatile("cp.async.cg.shared.global [%0], [%1], 16;" :: "r"(dst), "l"(src));
}
#define CPA_COMMIT() asm volatile("cp.async.commit_group;" ::: "memory")
#define CPA_WAIT1()  asm volatile("cp.async.wait_group 1;" ::: "memory")
#define CPA_WAIT0()  asm volatile("cp.async.wait_group 0;" ::: "memory")

__device__ __forceinline__ uint32_t pack_f16x2(float a, float b) {
    __half2 h = __floats2half2_rn(a, b);
    return *(uint32_t*)&h;
}
// fp16 hi/lo split (used only for P in attention)
__device__ __forceinline__ void hilo_pair_f16(float a, float b, uint32_t& h, uint32_t& l) {
    __half ha = __float2half_rn(a), hb = __float2half_rn(b);
    __half la = __float2half_rn(a - __half2float(ha));
    __half lb = __float2half_rn(b - __half2float(hb));
    h = (uint32_t)__half_as_ushort(ha) | ((uint32_t)__half_as_ushort(hb) << 16);
    l = (uint32_t)__half_as_ushort(la) | ((uint32_t)__half_as_ushort(lb) << 16);
}

// =================================================================================
// Conversion kernels
// =================================================================================
__global__ void conv_x_kernel(const float* __restrict__ x) {
    size_t i = ((size_t)blockIdx.x * 256 + threadIdx.x) * 4;
    float4 v = *(const float4*)(x + i);
    *(uint32_t*)(g_xhi + i)     = pack_f16x2(v.x, v.y);
    *(uint32_t*)(g_xhi + i + 2) = pack_f16x2(v.z, v.w);
}

__global__ void conv_w_kernel(const float* __restrict__ Wq, const float* __restrict__ Wk,
                              const float* __restrict__ Wv) {
    int idx = blockIdx.x * 256 + threadIdx.x;   // n*C + k
    if (idx >= NQKV * C) return;
    int n = idx / C, k = idx - n * C;
    int which = n / HD, rem = n - which * HD;
    int h = rem >> 6, d = rem & 63;
    const float* W = (which == 0) ? Wq : (which == 1) ? Wk : Wv;
    g_wthi[idx] = __float2half_rn(W[((size_t)h * C + k) * D + d]);
}

__global__ void conv_wp_kernel(const float* __restrict__ Wp) {
    int idx = blockIdx.x * 256 + threadIdx.x;   // n*C + k
    if (idx >= HD * C) return;
    int n = idx / C, k = idx - n * C;
    g_wpthi[idx] = __float2half_rn(Wp[(size_t)k * C + n]);
}

// =================================================================================
// Pure fp16 GEMM: Y[128 x 128] = A[128 x 384] @ B[n][k]^T.  (at HMMA-f32acc ceiling)
// =================================================================================
#define STAGE_BYTES 32768
#define GEMM_SMEM (2 * STAGE_BYTES)

template <bool PROJ>
__global__ __launch_bounds__(256, 2)
void mma_gemm(const float* __restrict__ bp, float* __restrict__ out)
{
    extern __shared__ __align__(1024) char sm[];
    const uint32_t smb = smem_u32(sm);
    const int tid = threadIdx.x, wid = tid >> 5, lane = tid & 31;
    const int b = blockIdx.y, n0 = blockIdx.x * 128;
    const int wm = (wid >> 2) * 64;     // 0,64
    const int wn = (wid & 3) * 32;      // 0,32,64,96

    const __half* __restrict__ Ahi = (PROJ ? g_atthi : g_xhi) + (size_t)b * T * C;
    const __half* __restrict__ Bhi = (PROJ ? g_wpthi : g_wthi) + (size_t)n0 * C;

    const int l_row = tid >> 3;          // 0..31
    const int l_seg = tid & 7;

    auto load_chunk = [&](int c, int s) {
        const int c0 = c * 64;
        const uint32_t sb = smb + s * STAGE_BYTES;
#pragma unroll
        for (int p = 0; p < 4; p++) {
            const int row = l_row + p * 32;
            const uint32_t doff = (uint32_t)(row * 128 + ((l_seg ^ (row & 7)) << 4));
            const size_t soff = (size_t)row * C + c0 + l_seg * 8;
            cpa16(sb + doff,         Ahi + soff);
            cpa16(sb + 16384 + doff, Bhi + soff);
        }
        CPA_COMMIT();
    };

    float acc[4][4][4];
#pragma unroll
    for (int i = 0; i < 4; i++)
#pragma unroll
        for (int j = 0; j < 4; j++)
#pragma unroll
            for (int e = 0; e < 4; e++) acc[i][j][e] = 0.f;

    const int rA  = (lane & 7) + ((lane >> 3) & 1) * 8;
    const int khA = lane >> 4;
    const int swA = rA & 7;
    const int rB  = (lane & 7) + (lane >> 4) * 8;
    const int khB = (lane >> 3) & 1;
    const int swB = rB & 7;

    load_chunk(0, 0);
    load_chunk(1, 1);

    for (int c = 0; c < 6; c++) {
        if (c == 5) CPA_WAIT0(); else CPA_WAIT1();
        __syncthreads();

        const uint32_t sb = smb + (c & 1) * STAGE_BYTES;
        const uint32_t aBase = sb + (uint32_t)((wm + rA) * 128);
        const uint32_t bBase = sb + 16384 + (uint32_t)((wn + rB) * 128);

#pragma unroll
        for (int ks = 0; ks < 4; ks++) {
            const uint32_t aoff = (uint32_t)(((ks * 2 + khA) ^ swA) << 4);
            const uint32_t boff = (uint32_t)(((ks * 2 + khB) ^ swB) << 4);
            uint32_t ah[4][4], bh[2][4];
            ldsm4(ah[0], aBase + aoff);
            ldsm4(bh[0], bBase + boff);
            ldsm4(ah[1], aBase + 2048 + aoff);
            ldsm4(bh[1], bBase + 2048 + boff);
            mma16816f(acc[0][0], ah[0], &bh[0][0]);
            mma16816f(acc[0][1], ah[0], &bh[0][2]);
            ldsm4(ah[2], aBase + 4096 + aoff);
            mma16816f(acc[0][2], ah[0], &bh[1][0]);
            mma16816f(acc[0][3], ah[0], &bh[1][2]);
            ldsm4(ah[3], aBase + 6144 + aoff);
            mma16816f(acc[1][0], ah[1], &bh[0][0]);
            mma16816f(acc[1][1], ah[1], &bh[0][2]);
            mma16816f(acc[1][2], ah[1], &bh[1][0]);
            mma16816f(acc[1][3], ah[1], &bh[1][2]);
#pragma unroll
            for (int mf = 2; mf < 4; mf++) {
                mma16816f(acc[mf][0], ah[mf], &bh[0][0]);
                mma16816f(acc[mf][1], ah[mf], &bh[0][2]);
                mma16816f(acc[mf][2], ah[mf], &bh[1][0]);
                mma16816f(acc[mf][3], ah[mf], &bh[1][2]);
            }
        }
        __syncthreads();
        if (c + 2 < 6) load_chunk(c + 2, (c & 1));
    }

    // ---------------- epilogue ----------------
    const int qrow = lane >> 2;
    const int qcol = (lane & 3) * 2;

    if (PROJ) {
#pragma unroll
        for (int mf = 0; mf < 4; mf++) {
#pragma unroll
            for (int nf = 0; nf < 4; nf++) {
                const int row = wm + mf * 16 + qrow;
                const int col = n0 + wn + nf * 8 + qcol;
                const float2 bb = *(const float2*)(bp + col);
                float* p0 = out + ((size_t)b * T + row) * HD + col;
                float* p1 = out + ((size_t)b * T + row + 8) * HD + col;
                *(float2*)p0 = make_float2(acc[mf][nf][0] + bb.x, acc[mf][nf][1] + bb.y);
                *(float2*)p1 = make_float2(acc[mf][nf][2] + bb.x, acc[mf][nf][3] + bb.y);
            }
        }
    } else {
        const int which = blockIdx.x / 3;       // 0=q,1=k,2=v (3 tiles of 128 per which)
        const int rem0 = (blockIdx.x % 3) * 128;
        __half* dst = (which == 0) ? g_q : (which == 1) ? g_k : g_v;
        const float scale = (which == 0) ? 0.125f : 1.0f;   // q pre-scaled by D^-1/2
#pragma unroll
        for (int mf = 0; mf < 4; mf++) {
#pragma unroll
            for (int nf = 0; nf < 4; nf++) {
                const int row = wm + mf * 16 + qrow;
                const int rem = rem0 + wn + nf * 8 + qcol;
                const int hh = rem >> 6, dd = rem & 63;
                const size_t o0 = (((size_t)(b * H + hh) * T) + row) * D + dd;
                *(uint32_t*)(dst + o0) =
                    pack_f16x2(acc[mf][nf][0] * scale, acc[mf][nf][1] * scale);
                *(uint32_t*)(dst + o0 + 8 * D) =
                    pack_f16x2(acc[mf][nf][2] * scale, acc[mf][nf][3] * scale);
            }
        }
    }
}

// =================================================================================
// MMA attention per (b, h): Q/K/V single fp16, P fp16 2-term (regs).
// smem: q@0 (16K), k@16K, v@32K => 48KB; 2 CTAs/SM.
// =================================================================================
#define ATTN_SMEM 49152

__global__ __launch_bounds__(256, 2)
void attn_mma()
{
    extern __shared__ __align__(1024) char sm[];
    const uint32_t smb = smem_u32(sm);
    const int tid = threadIdx.x, w = tid >> 5, lane = tid & 31;
    const int b = blockIdx.x, h = blockIdx.y;
    const int rb = (w < 4) ? w : (11 - w);     // row-block; SMSP pairs balanced

    const size_t blk = (size_t)(b * H + h) * (T * D);
    {
        const int seg = tid & 7;
#pragma unroll
        for (int p = 0; p < 4; p++) {
            const int row = (tid + p * 256) >> 3;          // 0..127
            const uint32_t doff = (uint32_t)(row * 128 + ((seg ^ (row & 7)) << 4));
            const size_t soff = blk + (size_t)row * D + seg * 8;
            cpa16(smb + doff,         g_q + soff);
            cpa16(smb + 16384 + doff, g_k + soff);
            cpa16(smb + 32768 + doff, g_v + soff);
        }
    }
    CPA_COMMIT();
    CPA_WAIT0();
    __syncthreads();

    const int rA  = (lane & 7) + ((lane >> 3) & 1) * 8;
    const int khA = lane >> 4;
    const int swA = rA & 7;
    const int rB  = (lane & 7) + (lane >> 4) * 8;
    const int khB = (lane >> 3) & 1;
    const int swB = rB & 7;

    const uint32_t aQ = smb + (uint32_t)((rb * 16 + rA) * 128);

    // ---------------- S = Q @ K^T (single term, causal block-skip) ----------------
    float S[16][4];
#pragma unroll
    for (int i = 0; i < 16; i++)
#pragma unroll
        for (int e = 0; e < 4; e++) S[i][e] = 0.f;

#pragma unroll
    for (int ks = 0; ks < 4; ks++) {
        uint32_t qh[4];
        const uint32_t aoff = (uint32_t)(((ks * 2 + khA) ^ swA) << 4);
        ldsm4(qh, aQ + aoff);
        const uint32_t boff = (uint32_t)(((ks * 2 + khB) ^ swB) << 4);
#pragma unroll
        for (int g = 0; g < 8; g += 2) {
            if (g > rb) break;
            uint32_t kh0[4];
            const uint32_t bb0 = smb + 16384 + (uint32_t)((g * 16 + rB) * 128);
            ldsm4(kh0, bb0 + boff);
            const bool g1ok = (g + 1) <= rb;
            uint32_t kh1[4];
            if (g1ok) {
                const uint32_t bb1 = smb + 16384 + (uint32_t)(((g + 1) * 16 + rB) * 128);
                ldsm4(kh1, bb1 + boff);
            }
            mma16816f(S[2 * g],     qh, &kh0[0]);
            mma16816f(S[2 * g + 1], qh, &kh0[2]);
            if (g1ok) {
                mma16816f(S[2 * g + 2], qh, &kh1[0]);
                mma16816f(S[2 * g + 3], qh, &kh1[2]);
            }
        }
    }

    // ---------------- softmax exponentials (q pre-scaled by D^-1/2) ----------
    const int row0 = rb * 16 + (lane >> 2);
    const int row1 = row0 + 8;
    const int colb = 2 * (lane & 3);
    float sum0 = 0.f, sum1 = 0.f;
#pragma unroll
    for (int nf = 0; nf < 16; nf++) {
        if (nf > 2 * rb + 1) break;
        const int c0 = nf * 8 + colb, c1 = c0 + 1;
        float e00 = (c0 <= row0) ? __expf(S[nf][0]) : 0.f;
        float e01 = (c1 <= row0) ? __expf(S[nf][1]) : 0.f;
        float e10 = (c0 <= row1) ? __expf(S[nf][2]) : 0.f;
        float e11 = (c1 <= row1) ? __expf(S[nf][3]) : 0.f;
        S[nf][0] = e00; S[nf][1] = e01; S[nf][2] = e10; S[nf][3] = e11;
        sum0 += e00 + e01;
        sum1 += e10 + e11;
    }
    sum0 += __shfl_xor_sync(0xFFFFFFFFu, sum0, 1);
    sum0 += __shfl_xor_sync(0xFFFFFFFFu, sum0, 2);
    sum1 += __shfl_xor_sync(0xFFFFFFFFu, sum1, 1);
    sum1 += __shfl_xor_sync(0xFFFFFFFFu, sum1, 2);
    const float inv0 = 1.0f / sum0;
    const float inv1 = 1.0f / sum1;

    // ---------------- O = (raw P) @ V; P fp16 hi/lo, V single fp16 --------
    float O[8][4];
#pragma unroll
    for (int i = 0; i < 8; i++)
#pragma unroll
        for (int e = 0; e < 4; e++) O[i][e] = 0.f;

    const int mT = lane >> 3;
    const int rT = lane & 7;

#pragma unroll
    for (int ks = 0; ks < 8; ks++) {
        if (ks > rb) break;
        const int srow = ks * 16 + (mT & 1) * 8 + rT;
        const uint32_t rowOff = (uint32_t)(srow * 128);
        uint32_t vh[4][4];
        {
            const int dseg0 = (mT >> 1);
            const uint32_t a0 = rowOff + (uint32_t)(((dseg0 ^ (srow & 7)) << 4));
            ldsm4t(vh[0], smb + 32768 + a0);
        }
        uint32_t phi[4], plo[4];
        hilo_pair_f16(S[2 * ks][0],     S[2 * ks][1],     phi[0], plo[0]);
        hilo_pair_f16(S[2 * ks][2],     S[2 * ks][3],     phi[1], plo[1]);
        hilo_pair_f16(S[2 * ks + 1][0], S[2 * ks + 1][1], phi[2], plo[2]);
        hilo_pair_f16(S[2 * ks + 1][2], S[2 * ks + 1][3], phi[3], plo[3]);
#pragma unroll
        for (int g = 1; g < 4; g++) {
            const int dseg = g * 2 + (mT >> 1);
            const uint32_t addr = rowOff + (uint32_t)(((dseg ^ (srow & 7)) << 4));
            ldsm4t(vh[g], smb + 32768 + addr);
            mma16816f(O[2 * (g - 1)],     phi, &vh[g - 1][0]);
            mma16816f(O[2 * (g - 1) + 1], phi, &vh[g - 1][2]);
            mma16816f(O[2 * (g - 1)],     plo, &vh[g - 1][0]);
            mma16816f(O[2 * (g - 1) + 1], plo, &vh[g - 1][2]);
        }
        mma16816f(O[6], phi, &vh[3][0]);
        mma16816f(O[7], phi, &vh[3][2]);
        mma16816f(O[6], plo, &vh[3][0]);
        mma16816f(O[7], plo, &vh[3][2]);
    }

    // ---------------- epilogue: normalize, att fp16 [b][t][h*64+d] ---------
    const size_t obase = (size_t)b * T * HD + h * D;
#pragma unroll
    for (int nf = 0; nf < 8; nf++) {
        const int d0 = nf * 8 + colb;
        *(uint32_t*)(g_atthi + obase + (size_t)row0 * HD + d0) =
            pack_f16x2(O[nf][0] * inv0, O[nf][1] * inv0);
        *(uint32_t*)(g_atthi + obase + (size_t)row1 * HD + d0) =
            pack_f16x2(O[nf][2] * inv1, O[nf][3] * inv1);
    }
}

// =================================================================================
extern "C" void kernel_launch(void* const* d_in, const int* in_sizes, int n_in,
                              void* d_out, int out_size)
{
    (void)in_sizes; (void)n_in; (void)out_size;
    const float* x  = (const float*)d_in[0];
    const float* Wq = (const float*)d_in[1];
    const float* Wk = (const float*)d_in[2];
    const float* Wv = (const float*)d_in[3];
    const float* Wp = (const float*)d_in[4];
    const float* bp = (const float*)d_in[5];
    float* out = (float*)d_out;

    cudaFuncSetAttribute(mma_gemm<false>, cudaFuncAttributeMaxDynamicSharedMemorySize, GEMM_SMEM);
    cudaFuncSetAttribute(mma_gemm<true>,  cudaFuncAttributeMaxDynamicSharedMemorySize, GEMM_SMEM);
    cudaFuncSetAttribute(attn_mma, cudaFuncAttributeMaxDynamicSharedMemorySize, ATTN_SMEM);

    conv_x_kernel<<<(BATCH * T * C / 4) / 256, 256>>>(x);
    conv_w_kernel<<<(NQKV * C + 255) / 256, 256>>>(Wq, Wk, Wv);
    conv_wp_kernel<<<(HD * C + 255) / 256, 256>>>(Wp);

    mma_gemm<false><<<dim3(9, BATCH), 256, GEMM_SMEM>>>(nullptr, nullptr);
    attn_mma<<<dim3(BATCH, H), 256, ATTN_SMEM>>>();
    mma_gemm<true><<<dim3(3, BATCH), 256, GEMM_SMEM>>>(bp, out);
}

// round 13
// speedup vs baseline: 2.4560x; 1.0379x over previous
#include <cuda_runtime.h>
#include <cuda_fp16.h>
#include <cstdint>

#define BATCH 512
#define T 128
#define C 384
#define H 6
#define D 64
#define HD 384
#define NQKV 1152

// ---------------- scratch (device globals; no runtime allocation) ----------------
__device__ __align__(256) __half g_xhi[(size_t)BATCH * T * C];
__device__ __align__(256) __half g_wthi[(size_t)NQKV * C];    // [n][k]
__device__ __align__(256) __half g_wpthi[(size_t)HD * C];     // [n][k] = Wp[k][n]
__device__ __align__(256) __half g_atthi[(size_t)BATCH * T * HD];
// q (pre-scaled D^-1/2), k, v single fp16; all [b][h][t][d]
__device__ __align__(256) __half g_q[(size_t)BATCH * H * T * D];
__device__ __align__(256) __half g_k[(size_t)BATCH * H * T * D];
__device__ __align__(256) __half g_v[(size_t)BATCH * H * T * D];

// ---------------- helpers (baseline PTX, compute_103-safe) ----------------
__device__ __forceinline__ uint32_t smem_u32(const void* p) {
    uint32_t a;
    asm("{ .reg .u64 t; cvta.to.shared.u64 t, %1; cvt.u32.u64 %0, t; }" : "=r"(a) : "l"(p));
    return a;
}
__device__ __forceinline__ void ldsm4(uint32_t* r, uint32_t addr) {
    asm volatile("ldmatrix.sync.aligned.m8n8.x4.shared.b16 {%0,%1,%2,%3}, [%4];"
        : "=r"(r[0]), "=r"(r[1]), "=r"(r[2]), "=r"(r[3]) : "r"(addr));
}
__device__ __forceinline__ void ldsm4t(uint32_t* r, uint32_t addr) {
    asm volatile("ldmatrix.sync.aligned.m8n8.x4.trans.shared.b16 {%0,%1,%2,%3}, [%4];"
        : "=r"(r[0]), "=r"(r[1]), "=r"(r[2]), "=r"(r[3]) : "r"(addr));
}
// fp16 MMA, fp32 accum
__device__ __forceinline__ void mma16816f(float* c, const uint32_t* a, const uint32_t* b) {
    asm volatile("mma.sync.aligned.m16n8k16.row.col.f32.f16.f16.f32 "
        "{%0,%1,%2,%3}, {%4,%5,%6,%7}, {%8,%9}, {%0,%1,%2,%3};"
        : "+f"(c[0]), "+f"(c[1]), "+f"(c[2]), "+f"(c[3])
        : "r"(a[0]), "r"(a[1]), "r"(a[2]), "r"(a[3]), "r"(b[0]), "r"(b[1]));
}
__device__ __forceinline__ void cpa16(uint32_t dst, const void* src) {
    asm volatile("cp.async.cg.shared.global [%0], [%1], 16;" :: "r"(dst), "l"(src));
}
#define CPA_COMMIT() asm volatile("cp.async.commit_group;" ::: "memory")
#define CPA_WAIT2()  asm volatile("cp.async.wait_group 2;" ::: "memory")
#define CPA_WAIT1()  asm volatile("cp.async.wait_group 1;" ::: "memory")
#define CPA_WAIT0()  asm volatile("cp.async.wait_group 0;" ::: "memory")

__device__ __forceinline__ uint32_t pack_f16x2(float a, float b) {
    __half2 h = __floats2half2_rn(a, b);
    return *(uint32_t*)&h;
}

// =================================================================================
// Fused conversion kernel: x -> fp16, Wq/Wk/Wv -> wt[n][k], Wp -> wpt[n][k]
// grid: [0, NB_X) x-blocks, [NB_X, NB_X+NB_W) w-blocks, rest wp-blocks.
// =================================================================================
#define NB_X  ((BATCH * T * C / 4) / 256)          // 24576
#define NB_W  ((NQKV * C + 255) / 256)             // 1728
#define NB_WP ((HD * C + 255) / 256)               // 576

__global__ void conv_all_kernel(const float* __restrict__ x,
                                const float* __restrict__ Wq, const float* __restrict__ Wk,
                                const float* __restrict__ Wv, const float* __restrict__ Wp)
{
    const int bid = blockIdx.x;
    if (bid < NB_X) {
        size_t i = ((size_t)bid * 256 + threadIdx.x) * 4;
        float4 v = *(const float4*)(x + i);
        *(uint32_t*)(g_xhi + i)     = pack_f16x2(v.x, v.y);
        *(uint32_t*)(g_xhi + i + 2) = pack_f16x2(v.z, v.w);
    } else if (bid < NB_X + NB_W) {
        int idx = (bid - NB_X) * 256 + threadIdx.x;   // n*C + k
        if (idx >= NQKV * C) return;
        int n = idx / C, k = idx - n * C;
        int which = n / HD, rem = n - which * HD;
        int h = rem >> 6, d = rem & 63;
        const float* W = (which == 0) ? Wq : (which == 1) ? Wk : Wv;
        g_wthi[idx] = __float2half_rn(W[((size_t)h * C + k) * D + d]);
    } else {
        int idx = (bid - NB_X - NB_W) * 256 + threadIdx.x;   // n*C + k
        if (idx >= HD * C) return;
        int n = idx / C, k = idx - n * C;
        g_wpthi[idx] = __float2half_rn(Wp[(size_t)k * C + n]);
    }
}

// =================================================================================
// Pure fp16 GEMM: Y[128 x 128] = A[128 x 384] @ B[n][k]^T. 3-stage cp.async pipeline.
// Stage (32KB): A@0 (16K), B@16K (16K); 3 stages = 96KB; 2 CTAs/SM.
// =================================================================================
#define STAGE_BYTES 32768
#define GEMM_SMEM (3 * STAGE_BYTES)

template <bool PROJ>
__global__ __launch_bounds__(256, 2)
void mma_gemm(const float* __restrict__ bp, float* __restrict__ out)
{
    extern __shared__ __align__(1024) char sm[];
    const uint32_t smb = smem_u32(sm);
    const int tid = threadIdx.x, wid = tid >> 5, lane = tid & 31;
    const int b = blockIdx.y, n0 = blockIdx.x * 128;
    const int wm = (wid >> 2) * 64;     // 0,64
    const int wn = (wid & 3) * 32;      // 0,32,64,96

    const __half* __restrict__ Ahi = (PROJ ? g_atthi : g_xhi) + (size_t)b * T * C;
    const __half* __restrict__ Bhi = (PROJ ? g_wpthi : g_wthi) + (size_t)n0 * C;

    const int l_row = tid >> 3;          // 0..31
    const int l_seg = tid & 7;

    auto load_chunk = [&](int c) {
        const int c0 = c * 64;
        const uint32_t sb = smb + (c % 3) * STAGE_BYTES;
#pragma unroll
        for (int p = 0; p < 4; p++) {
            const int row = l_row + p * 32;
            const uint32_t doff = (uint32_t)(row * 128 + ((l_seg ^ (row & 7)) << 4));
            const size_t soff = (size_t)row * C + c0 + l_seg * 8;
            cpa16(sb + doff,         Ahi + soff);
            cpa16(sb + 16384 + doff, Bhi + soff);
        }
        CPA_COMMIT();
    };

    float acc[4][4][4];
#pragma unroll
    for (int i = 0; i < 4; i++)
#pragma unroll
        for (int j = 0; j < 4; j++)
#pragma unroll
            for (int e = 0; e < 4; e++) acc[i][j][e] = 0.f;

    const int rA  = (lane & 7) + ((lane >> 3) & 1) * 8;
    const int khA = lane >> 4;
    const int swA = rA & 7;
    const int rB  = (lane & 7) + (lane >> 4) * 8;
    const int khB = (lane >> 3) & 1;
    const int swB = rB & 7;

    load_chunk(0);
    load_chunk(1);
    load_chunk(2);

    for (int c = 0; c < 6; c++) {
        if (c < 4) CPA_WAIT2(); else if (c == 4) CPA_WAIT1(); else CPA_WAIT0();
        __syncthreads();

        const uint32_t sb = smb + (c % 3) * STAGE_BYTES;
        const uint32_t aBase = sb + (uint32_t)((wm + rA) * 128);
        const uint32_t bBase = sb + 16384 + (uint32_t)((wn + rB) * 128);

#pragma unroll
        for (int ks = 0; ks < 4; ks++) {
            const uint32_t aoff = (uint32_t)(((ks * 2 + khA) ^ swA) << 4);
            const uint32_t boff = (uint32_t)(((ks * 2 + khB) ^ swB) << 4);
            uint32_t ah[4][4], bh[2][4];
            ldsm4(ah[0], aBase + aoff);
            ldsm4(bh[0], bBase + boff);
            ldsm4(ah[1], aBase + 2048 + aoff);
            ldsm4(bh[1], bBase + 2048 + boff);
            mma16816f(acc[0][0], ah[0], &bh[0][0]);
            mma16816f(acc[0][1], ah[0], &bh[0][2]);
            ldsm4(ah[2], aBase + 4096 + aoff);
            mma16816f(acc[0][2], ah[0], &bh[1][0]);
            mma16816f(acc[0][3], ah[0], &bh[1][2]);
            ldsm4(ah[3], aBase + 6144 + aoff);
            mma16816f(acc[1][0], ah[1], &bh[0][0]);
            mma16816f(acc[1][1], ah[1], &bh[0][2]);
            mma16816f(acc[1][2], ah[1], &bh[1][0]);
            mma16816f(acc[1][3], ah[1], &bh[1][2]);
#pragma unroll
            for (int mf = 2; mf < 4; mf++) {
                mma16816f(acc[mf][0], ah[mf], &bh[0][0]);
                mma16816f(acc[mf][1], ah[mf], &bh[0][2]);
                mma16816f(acc[mf][2], ah[mf], &bh[1][0]);
                mma16816f(acc[mf][3], ah[mf], &bh[1][2]);
            }
        }
        __syncthreads();
        if (c + 3 < 6) load_chunk(c + 3);
    }

    // ---------------- epilogue ----------------
    const int qrow = lane >> 2;
    const int qcol = (lane & 3) * 2;

    if (PROJ) {
#pragma unroll
        for (int mf = 0; mf < 4; mf++) {
#pragma unroll
            for (int nf = 0; nf < 4; nf++) {
                const int row = wm + mf * 16 + qrow;
                const int col = n0 + wn + nf * 8 + qcol;
                const float2 bb = *(const float2*)(bp + col);
                float* p0 = out + ((size_t)b * T + row) * HD + col;
                float* p1 = out + ((size_t)b * T + row + 8) * HD + col;
                *(float2*)p0 = make_float2(acc[mf][nf][0] + bb.x, acc[mf][nf][1] + bb.y);
                *(float2*)p1 = make_float2(acc[mf][nf][2] + bb.x, acc[mf][nf][3] + bb.y);
            }
        }
    } else {
        const int which = blockIdx.x / 3;       // 0=q,1=k,2=v (3 tiles of 128 per which)
        const int rem0 = (blockIdx.x % 3) * 128;
        __half* dst = (which == 0) ? g_q : (which == 1) ? g_k : g_v;
        const float scale = (which == 0) ? 0.125f : 1.0f;   // q pre-scaled by D^-1/2
#pragma unroll
        for (int mf = 0; mf < 4; mf++) {
#pragma unroll
            for (int nf = 0; nf < 4; nf++) {
                const int row = wm + mf * 16 + qrow;
                const int rem = rem0 + wn + nf * 8 + qcol;
                const int hh = rem >> 6, dd = rem & 63;
                const size_t o0 = (((size_t)(b * H + hh) * T) + row) * D + dd;
                *(uint32_t*)(dst + o0) =
                    pack_f16x2(acc[mf][nf][0] * scale, acc[mf][nf][1] * scale);
                *(uint32_t*)(dst + o0 + 8 * D) =
                    pack_f16x2(acc[mf][nf][2] * scale, acc[mf][nf][3] * scale);
            }
        }
    }
}

// =================================================================================
// MMA attention per (b, h): Q/K/V/P all single fp16, fp32 accum.
// smem: q@0 (16K), k@16K, v@32K => 48KB; 2 CTAs/SM.
// =================================================================================
#define ATTN_SMEM 49152

__global__ __launch_bounds__(256, 2)
void attn_mma()
{
    extern __shared__ __align__(1024) char sm[];
    const uint32_t smb = smem_u32(sm);
    const int tid = threadIdx.x, w = tid >> 5, lane = tid & 31;
    const int b = blockIdx.x, h = blockIdx.y;
    const int rb = (w < 4) ? w : (11 - w);     // row-block; SMSP pairs balanced

    const size_t blk = (size_t)(b * H + h) * (T * D);
    {
        const int seg = tid & 7;
#pragma unroll
        for (int p = 0; p < 4; p++) {
            const int row = (tid + p * 256) >> 3;          // 0..127
            const uint32_t doff = (uint32_t)(row * 128 + ((seg ^ (row & 7)) << 4));
            const size_t soff = blk + (size_t)row * D + seg * 8;
            cpa16(smb + doff,         g_q + soff);
            cpa16(smb + 16384 + doff, g_k + soff);
            cpa16(smb + 32768 + doff, g_v + soff);
        }
    }
    CPA_COMMIT();
    CPA_WAIT0();
    __syncthreads();

    const int rA  = (lane & 7) + ((lane >> 3) & 1) * 8;
    const int khA = lane >> 4;
    const int swA = rA & 7;
    const int rB  = (lane & 7) + (lane >> 4) * 8;
    const int khB = (lane >> 3) & 1;
    const int swB = rB & 7;

    const uint32_t aQ = smb + (uint32_t)((rb * 16 + rA) * 128);

    // ---------------- S = Q @ K^T (single term, causal block-skip) ----------------
    float S[16][4];
#pragma unroll
    for (int i = 0; i < 16; i++)
#pragma unroll
        for (int e = 0; e < 4; e++) S[i][e] = 0.f;

#pragma unroll
    for (int ks = 0; ks < 4; ks++) {
        uint32_t qh[4];
        const uint32_t aoff = (uint32_t)(((ks * 2 + khA) ^ swA) << 4);
        ldsm4(qh, aQ + aoff);
        const uint32_t boff = (uint32_t)(((ks * 2 + khB) ^ swB) << 4);
#pragma unroll
        for (int g = 0; g < 8; g += 2) {
            if (g > rb) break;
            uint32_t kh0[4];
            const uint32_t bb0 = smb + 16384 + (uint32_t)((g * 16 + rB) * 128);
            ldsm4(kh0, bb0 + boff);
            const bool g1ok = (g + 1) <= rb;
            uint32_t kh1[4];
            if (g1ok) {
                const uint32_t bb1 = smb + 16384 + (uint32_t)(((g + 1) * 16 + rB) * 128);
                ldsm4(kh1, bb1 + boff);
            }
            mma16816f(S[2 * g],     qh, &kh0[0]);
            mma16816f(S[2 * g + 1], qh, &kh0[2]);
            if (g1ok) {
                mma16816f(S[2 * g + 2], qh, &kh1[0]);
                mma16816f(S[2 * g + 3], qh, &kh1[2]);
            }
        }
    }

    // ---------------- softmax exponentials (q pre-scaled by D^-1/2) ----------
    const int row0 = rb * 16 + (lane >> 2);
    const int row1 = row0 + 8;
    const int colb = 2 * (lane & 3);
    float sum0 = 0.f, sum1 = 0.f;
#pragma unroll
    for (int nf = 0; nf < 16; nf++) {
        if (nf > 2 * rb + 1) break;
        const int c0 = nf * 8 + colb, c1 = c0 + 1;
        float e00 = (c0 <= row0) ? __expf(S[nf][0]) : 0.f;
        float e01 = (c1 <= row0) ? __expf(S[nf][1]) : 0.f;
        float e10 = (c0 <= row1) ? __expf(S[nf][2]) : 0.f;
        float e11 = (c1 <= row1) ? __expf(S[nf][3]) : 0.f;
        S[nf][0] = e00; S[nf][1] = e01; S[nf][2] = e10; S[nf][3] = e11;
        sum0 += e00 + e01;
        sum1 += e10 + e11;
    }
    sum0 += __shfl_xor_sync(0xFFFFFFFFu, sum0, 1);
    sum0 += __shfl_xor_sync(0xFFFFFFFFu, sum0, 2);
    sum1 += __shfl_xor_sync(0xFFFFFFFFu, sum1, 1);
    sum1 += __shfl_xor_sync(0xFFFFFFFFu, sum1, 2);
    const float inv0 = 1.0f / sum0;
    const float inv1 = 1.0f / sum1;

    // ---------------- O = (raw P) @ V; P single fp16, V single fp16 --------
    float O[8][4];
#pragma unroll
    for (int i = 0; i < 8; i++)
#pragma unroll
        for (int e = 0; e < 4; e++) O[i][e] = 0.f;

    const int mT = lane >> 3;
    const int rT = lane & 7;

#pragma unroll
    for (int ks = 0; ks < 8; ks++) {
        if (ks > rb) break;
        const int srow = ks * 16 + (mT & 1) * 8 + rT;
        const uint32_t rowOff = (uint32_t)(srow * 128);
        uint32_t vh[4][4];
        {
            const int dseg0 = (mT >> 1);
            const uint32_t a0 = rowOff + (uint32_t)(((dseg0 ^ (srow & 7)) << 4));
            ldsm4t(vh[0], smb + 32768 + a0);
        }
        uint32_t phi[4];
        phi[0] = pack_f16x2(S[2 * ks][0],     S[2 * ks][1]);
        phi[1] = pack_f16x2(S[2 * ks][2],     S[2 * ks][3]);
        phi[2] = pack_f16x2(S[2 * ks + 1][0], S[2 * ks + 1][1]);
        phi[3] = pack_f16x2(S[2 * ks + 1][2], S[2 * ks + 1][3]);
#pragma unroll
        for (int g = 1; g < 4; g++) {
            const int dseg = g * 2 + (mT >> 1);
            const uint32_t addr = rowOff + (uint32_t)(((dseg ^ (srow & 7)) << 4));
            ldsm4t(vh[g], smb + 32768 + addr);
            mma16816f(O[2 * (g - 1)],     phi, &vh[g - 1][0]);
            mma16816f(O[2 * (g - 1) + 1], phi, &vh[g - 1][2]);
        }
        mma16816f(O[6], phi, &vh[3][0]);
        mma16816f(O[7], phi, &vh[3][2]);
    }

    // ---------------- epilogue: normalize, att fp16 [b][t][h*64+d] ---------
    const size_t obase = (size_t)b * T * HD + h * D;
#pragma unroll
    for (int nf = 0; nf < 8; nf++) {
        const int d0 = nf * 8 + colb;
        *(uint32_t*)(g_atthi + obase + (size_t)row0 * HD + d0) =
            pack_f16x2(O[nf][0] * inv0, O[nf][1] * inv0);
        *(uint32_t*)(g_atthi + obase + (size_t)row1 * HD + d0) =
            pack_f16x2(O[nf][2] * inv1, O[nf][3] * inv1);
    }
}

// =================================================================================
extern "C" void kernel_launch(void* const* d_in, const int* in_sizes, int n_in,
                              void* d_out, int out_size)
{
    (void)in_sizes; (void)n_in; (void)out_size;
    const float* x  = (const float*)d_in[0];
    const float* Wq = (const float*)d_in[1];
    const float* Wk = (const float*)d_in[2];
    const float* Wv = (const float*)d_in[3];
    const float* Wp = (const float*)d_in[4];
    const float* bp = (const float*)d_in[5];
    float* out = (float*)d_out;

    cudaFuncSetAttribute(mma_gemm<false>, cudaFuncAttributeMaxDynamicSharedMemorySize, GEMM_SMEM);
    cudaFuncSetAttribute(mma_gemm<true>,  cudaFuncAttributeMaxDynamicSharedMemorySize, GEMM_SMEM);
    cudaFuncSetAttribute(attn_mma, cudaFuncAttributeMaxDynamicSharedMemorySize, ATTN_SMEM);

    conv_all_kernel<<<NB_X + NB_W + NB_WP, 256>>>(x, Wq, Wk, Wv, Wp);

    mma_gemm<false><<<dim3(9, BATCH), 256, GEMM_SMEM>>>(nullptr, nullptr);
    attn_mma<<<dim3(BATCH, H), 256, ATTN_SMEM>>>();
    mma_gemm<true><<<dim3(3, BATCH), 256, GEMM_SMEM>>>(bp, out);
}